// round 11
// baseline (speedup 1.0000x reference)
#include <cuda_runtime.h>
#include <cuda_bf16.h>
#include <math.h>
#include <stdint.h>

#define B 32
#define T 8192
#define H 192
#define BT (B*T)
#define BINS 10
#define TAILV 5.0f
#define NJ 29

// residual stream ping-pong buffers (f32), layout [b][t][c]
__device__ float g_x0[(size_t)BT*H];
__device__ float g_x1[(size_t)BT*H];
// chunk-ordered pw weight image: [layer][chunk12][dtype2][o192][seg2][8bf16]
__device__ __align__(16) __nv_bfloat16 g_wr[3*12*2*192*16];
// chunk-ordered proj weight image: [chunk12][dtype2][o32][seg2][8bf16]
__device__ __align__(16) __nv_bfloat16 g_pr[12*2*32*16];
// transposed depthwise weights: [layer][tap][c]
__device__ float g_dwt[3*3*192];

// fast gelu: v - v/(exp(2c(v+av^3))+1); tails exact, |err|<~2e-4 abs
__device__ __forceinline__ float gelu_fast(float v){
    float t2 = 1.5957691216057308f * fmaf(0.044715f*v, v*v, v);
    float e = __expf(t2);
    float r;
    asm("rcp.approx.f32 %0, %1;" : "=f"(r) : "f"(e + 1.0f));
    return fmaf(-v, r, v);
}

// split (y0,y1) into packed bf16x2 hi + lo parts
__device__ __forceinline__ void split2(float y0, float y1, uint32_t& ph, uint32_t& pl){
    uint32_t h;
    asm("cvt.rn.bf16x2.f32 %0, %1, %2;" : "=r"(h) : "f"(y1), "f"(y0));
    float h0 = __uint_as_float(h << 16);
    float h1 = __uint_as_float(h & 0xffff0000u);
    asm("cvt.rn.bf16x2.f32 %0, %1, %2;" : "=r"(pl) : "f"(y1 - h1), "f"(y0 - h0));
    ph = h;
}

__device__ __forceinline__ uint32_t smem_u32(const void* p){
    uint32_t a;
    asm("{ .reg .u64 t; cvta.to.shared.u64 t, %1; cvt.u32.u64 %0, t; }" : "=r"(a) : "l"(p));
    return a;
}

#define LDSM4(r, addr) \
    asm volatile("ldmatrix.sync.aligned.m8n8.x4.shared.b16 {%0,%1,%2,%3}, [%4];" \
        : "=r"((r)[0]),"=r"((r)[1]),"=r"((r)[2]),"=r"((r)[3]) : "r"(addr))

#define MMA16816(d, a, b0, b1) \
    asm volatile("mma.sync.aligned.m16n8k16.row.col.f32.bf16.bf16.f32 " \
        "{%0,%1,%2,%3},{%4,%5,%6,%7},{%8,%9},{%0,%1,%2,%3};" \
        : "+f"((d)[0]),"+f"((d)[1]),"+f"((d)[2]),"+f"((d)[3]) \
        : "r"((a)[0]),"r"((a)[1]),"r"((a)[2]),"r"((a)[3]), "r"(b0),"r"(b1))

#define CP16(dst, src) \
    asm volatile("cp.async.cg.shared.global [%0], [%1], 16;" :: "r"(dst), "l"(src))
#define CP_COMMIT asm volatile("cp.async.commit_group;" ::: "memory")
#define CP_WAIT2  asm volatile("cp.async.wait_group 2;" ::: "memory")
#define CP_WAIT1  asm volatile("cp.async.wait_group 1;" ::: "memory")
#define CP_WAIT0  asm volatile("cp.async.wait_group 0;" ::: "memory")

// ---------------------------------------------------------------------------
__global__ void k_zero(float* __restrict__ out){
    out[(long long)B*2*T + threadIdx.x] = 0.0f;
}

// prep: pw chunk image, proj chunk image, dw transpose
__global__ void k_prep(const float* __restrict__ pw_w,
                       const float* __restrict__ proj_w,
                       const float* __restrict__ dw_w)
{
    int i = blockIdx.x*256 + threadIdx.x;
    if (i < 3*H*H){
        int L = i / (H*H);
        int r = i - L*(H*H);
        int o = r / H, k = r - o*H;
        float w = pw_w[i];
        __nv_bfloat16 hb = __float2bfloat16(w);
        __nv_bfloat16 lb = __float2bfloat16(w - __bfloat162float(hb));
        int ch = k >> 4;
        int s  = (k >> 3) & 1;
        int j  = k & 7;
        size_t base = (((size_t)(L*12 + ch)*2)*192 + o)*16 + s*8 + j;
        g_wr[base]        = hb;
        g_wr[base + 3072] = lb;
    }
    if (i < 12*2*32*16){
        // [ch][d][o][s][j]
        int ch = i >> 10;
        int rem = i & 1023;
        int d = rem >> 9;
        int rem2 = rem & 511;
        int o = rem2 >> 4;
        int s = (rem2 >> 3) & 1;
        int j = rem2 & 7;
        int k = ch*16 + s*8 + j;
        float w = (o < NJ) ? proj_w[o*H + k] : 0.0f;
        __nv_bfloat16 hb = __float2bfloat16(w);
        __nv_bfloat16 lb = __float2bfloat16(w - __bfloat162float(hb));
        g_pr[i] = d ? lb : hb;
    }
    if (i < 3*3*H){
        int L = i / (3*H);
        int rem = i - L*(3*H);
        int c = rem / 3, k = rem - c*3;
        g_dwt[L*(3*H) + k*H + c] = dw_w[i];
    }
}

// ---------------------------------------------------------------------------
// FUSED kernel: conv(dil)+LN1+gelu -> split-bf16 GEMM (W streamed, 4-stage
// ring) -> bias+LN2+gelu+residual. Last layer additionally: proj GEMM +
// RQ-spline + outputs + logdet, all in-CTA.
#define A_HI    0
#define A_LO    24576
#define BOFF    49152
#define BSTG    12288
#define PSM_OFF (BOFF + 24576)         // P matrix (64x33 f32) overlays B stages 2-3
#define PAR_OFF (BOFF + 4*BSTG)        // 98304
#define RED_OFF (PAR_OFF + 2304)       // red1 256f, red2 256f, mu 64f, rs 64f, redL 8f
#define FUSED_SMEM_BYTES (RED_OFF + 2592)

__global__ void __launch_bounds__(256,2) k_fused(int layer, int dil,
    const float* __restrict__ x,
    const float* __restrict__ in_w, const float* __restrict__ in_b,
    const float* __restrict__ xmask,
    const float* __restrict__ dw_b,
    const float* __restrict__ ln1_g, const float* __restrict__ ln1_b,
    const float* __restrict__ pw_b,
    const float* __restrict__ ln2_g, const float* __restrict__ ln2_b,
    const float* __restrict__ proj_b,
    float* __restrict__ out)
{
    extern __shared__ char smem[];
    uint32_t sbase = smem_u32(smem);
    int tid = threadIdx.x;
    int wid = tid >> 5, lane = tid & 31;
    int wm = wid & 1, wn = wid >> 1;          // 2 warps in M, 4 in N
    int q = lane >> 2, qi = lane & 3;
    long long bt0 = (long long)blockIdx.x * 64;
    int b  = (int)(bt0 >> 13);
    int t0 = (int)(bt0 & (T-1));
    bool first = (layer == 0), last = (layer == 2);
    const float* gin = last ? g_x1 : g_x0;
    float* gout = first ? g_x0 : g_x1;

    uint32_t dstB[3];
    #pragma unroll
    for(int m=0;m<3;m++){
        int id = tid + m*256;
        int d = id / 384;
        int rem = id - d*384;
        int o = rem >> 1, s = rem & 1;
        dstB[m] = (uint32_t)d*6144 + (uint32_t)o*32
                + (uint32_t)((s ^ ((o>>2)&1)) << 4);
    }
    const uint4* wrp = (const uint4*)g_wr + (size_t)layer*9216 + tid;

#define ISSUE(cc, st) do { \
    uint32_t _bs = sbase + BOFF + (uint32_t)(st)*BSTG; \
    const uint4* _w = wrp + (cc)*768; \
    CP16(_bs + dstB[0], _w); \
    CP16(_bs + dstB[1], _w + 256); \
    CP16(_bs + dstB[2], _w + 512); \
    CP_COMMIT; \
} while(0)

    ISSUE(0, 0);
    ISSUE(1, 1);
    ISSUE(2, 2);

    float* par = (float*)(smem + PAR_OFF);
    if(tid < 192){
        par[tid]       = pw_b[layer*H + tid];
        par[192 + tid] = ln2_g[layer*H + tid];
        par[384 + tid] = ln2_b[layer*H + tid];
    }

    // ---------------- phase 1: conv + LN1 + gelu -> A smem ----------------
    {
        int c0 = lane*6;
        float w0[6], w1[6], w2[6], bbv[6], ggv[6], gbv[6];
        const float* wt = g_dwt + layer*(3*H);
        #pragma unroll
        for(int p=0;p<3;p++){
            float2 a = *(const float2*)(wt + c0 + p*2);
            w0[p*2]=a.x; w0[p*2+1]=a.y;
            float2 bq = *(const float2*)(wt + H + c0 + p*2);
            w1[p*2]=bq.x; w1[p*2+1]=bq.y;
            float2 cq = *(const float2*)(wt + 2*H + c0 + p*2);
            w2[p*2]=cq.x; w2[p*2+1]=cq.y;
            float2 d = *(const float2*)(dw_b + layer*H + c0 + p*2);
            bbv[p*2]=d.x; bbv[p*2+1]=d.y;
            float2 e = *(const float2*)(ln1_g + layer*H + c0 + p*2);
            ggv[p*2]=e.x; ggv[p*2+1]=e.y;
            float2 f = *(const float2*)(ln1_b + layer*H + c0 + p*2);
            gbv[p*2]=f.x; gbv[p*2+1]=f.y;
        }
        float iw[6], ib[6];
        if(first){
            #pragma unroll
            for(int p=0;p<3;p++){
                float2 a = *(const float2*)(in_w + c0 + p*2);
                iw[p*2]=a.x; iw[p*2+1]=a.y;
                float2 bq = *(const float2*)(in_b + c0 + p*2);
                ib[p*2]=bq.x; ib[p*2+1]=bq.y;
            }
        }
        const float* mrow = xmask + (long long)b*T;
        const float* xrowa = x + ((long long)b*2)*T;

        #pragma unroll 1
        for(int rr=0; rr<8; rr++){
            int r = wid*8 + rr;
            long long grow = bt0 + r;
            int t = t0 + r;
            int tm = t - dil, tp = t + dil;
            bool hm = (tm >= 0), hp = (tp < T);
            float mm = hm ? mrow[tm] : 0.f;
            float m0 = mrow[t];
            float mp = hp ? mrow[tp] : 0.f;

            float xm[6], xz[6], xp[6];
            if(first){
                float xam = hm ? xrowa[tm] : 0.f;
                float xa0 = xrowa[t];
                float xap = hp ? xrowa[tp] : 0.f;
                #pragma unroll
                for(int k=0;k<6;k++){
                    xm[k] = iw[k]*xam + ib[k];
                    xz[k] = iw[k]*xa0 + ib[k];
                    xp[k] = iw[k]*xap + ib[k];
                }
            } else {
                const float* base = gin + grow*H + c0;
                #pragma unroll
                for(int p=0;p<3;p++){
                    float2 a = *(const float2*)(base + p*2);
                    xz[p*2]=a.x; xz[p*2+1]=a.y;
                }
                if(hm){
                    const float* bmp = base - (long long)dil*H;
                    #pragma unroll
                    for(int p=0;p<3;p++){
                        float2 a = *(const float2*)(bmp + p*2);
                        xm[p*2]=a.x; xm[p*2+1]=a.y;
                    }
                } else {
                    #pragma unroll
                    for(int k=0;k<6;k++) xm[k]=0.f;
                }
                if(hp){
                    const float* bpp = base + (long long)dil*H;
                    #pragma unroll
                    for(int p=0;p<3;p++){
                        float2 a = *(const float2*)(bpp + p*2);
                        xp[p*2]=a.x; xp[p*2+1]=a.y;
                    }
                } else {
                    #pragma unroll
                    for(int k=0;k<6;k++) xp[k]=0.f;
                }
            }

            float v[6];
            float s=0.f, sq=0.f;
            #pragma unroll
            for(int k=0;k<6;k++){
                float rv = w0[k]*(xm[k]*mm) + w1[k]*(xz[k]*m0) + w2[k]*(xp[k]*mp) + bbv[k];
                v[k]=rv; s+=rv; sq+=rv*rv;
            }
            #pragma unroll
            for(int o=16;o>0;o>>=1){
                s  += __shfl_xor_sync(0xffffffffu, s,  o);
                sq += __shfl_xor_sync(0xffffffffu, sq, o);
            }
            float mu = s*(1.0f/H);
            float rs = rsqrtf(sq*(1.0f/H) - mu*mu + 1e-5f);

            int xr = (r>>2)&1;
            #pragma unroll
            for(int p=0;p<3;p++){
                float y0 = gelu_fast((v[p*2]  -mu)*rs*ggv[p*2]   + gbv[p*2]);
                float y1 = gelu_fast((v[p*2+1]-mu)*rs*ggv[p*2+1] + gbv[p*2+1]);
                uint32_t ph, pl;
                split2(y0, y1, ph, pl);
                int c = c0 + 2*p;
                uint32_t off = (uint32_t)(c>>4)*2048 + (uint32_t)r*32
                             + (uint32_t)((((c>>3)&1) ^ xr) << 4) + (uint32_t)(c&7)*2;
                *(uint32_t*)(smem + A_HI + off) = ph;
                *(uint32_t*)(smem + A_LO + off) = pl;
            }
        }
    }

    // ---------------- phase 2: k-loop (12 chunks of k=16) ----------------
    int g2 = lane >> 3, lr = lane & 7;
    uint32_t aOff[2];
    #pragma unroll
    for(int mt=0;mt<2;mt++){
        int row = wm*32 + mt*16 + (g2&1)*8 + lr;
        aOff[mt] = (uint32_t)row*32 + (uint32_t)(((g2>>1) ^ ((row>>2)&1)) << 4);
    }
    uint32_t bOff[3];
    #pragma unroll
    for(int i=0;i<3;i++){
        int o = wn*48 + i*16 + (g2>>1)*8 + lr;
        bOff[i] = (uint32_t)o*32 + (uint32_t)(((g2&1) ^ ((o>>2)&1)) << 4);
    }

    float acc[2][6][4];
    #pragma unroll
    for(int mt=0;mt<2;mt++)
        #pragma unroll
        for(int nt=0;nt<6;nt++)
            #pragma unroll
            for(int r2=0;r2<4;r2++) acc[mt][nt][r2] = 0.f;

#define PASS(AH, BB) \
    _Pragma("unroll") \
    for(int mt=0;mt<2;mt++){ \
        _Pragma("unroll") \
        for(int i=0;i<3;i++){ \
            MMA16816(acc[mt][2*i],   AH[mt], BB[i][0], BB[i][1]); \
            MMA16816(acc[mt][2*i+1], AH[mt], BB[i][2], BB[i][3]); \
        } \
    }

    #pragma unroll 1
    for(int c=0;c<12;c++){
        if(c<10){ CP_WAIT2; } else if(c==10){ CP_WAIT1; } else { CP_WAIT0; }
        __syncthreads();
        if(c<9) ISSUE(c+3, (c+3)&3);
        uint32_t aB  = sbase + A_HI + (uint32_t)c*2048;
        uint32_t aBl = sbase + A_LO + (uint32_t)c*2048;
        uint32_t bB  = sbase + BOFF + (uint32_t)(c&3)*BSTG;

        uint32_t ah[2][4], al[2][4], bb[3][4];
        LDSM4(ah[0], aB  + aOff[0]);
        LDSM4(ah[1], aB  + aOff[1]);
        LDSM4(al[0], aBl + aOff[0]);
        LDSM4(al[1], aBl + aOff[1]);
        #pragma unroll
        for(int i=0;i<3;i++) LDSM4(bb[i], bB + bOff[i]);
        PASS(ah, bb)
        PASS(al, bb)
        #pragma unroll
        for(int i=0;i<3;i++) LDSM4(bb[i], bB + 6144 + bOff[i]);
        PASS(ah, bb)
    }
#undef PASS

    // ---------------- epilogue: bias + LN2 + gelu + residual ----------------
    float* red1 = (float*)(smem + RED_OFF);
    float* red2 = red1 + 256;
    float* musm = red1 + 512;
    float* rssm = red1 + 576;
    float* redL = red1 + 640;

    float s1[2][2] = {{0.f,0.f},{0.f,0.f}};
    float s2[2][2] = {{0.f,0.f},{0.f,0.f}};
    #pragma unroll
    for(int mt=0;mt<2;mt++)
        #pragma unroll
        for(int nt=0;nt<6;nt++){
            int col = wn*48 + nt*8 + qi*2;
            float b0 = par[col], b1 = par[col+1];
            acc[mt][nt][0] += b0; acc[mt][nt][1] += b1;
            acc[mt][nt][2] += b0; acc[mt][nt][3] += b1;
            #pragma unroll
            for(int h=0;h<2;h++){
                float v0 = acc[mt][nt][h*2], v1 = acc[mt][nt][h*2+1];
                s1[mt][h] += v0 + v1;
                s2[mt][h] += v0*v0 + v1*v1;
            }
        }
    __syncthreads();   // all warps past mainloop: A and B smem regions dead

    // last layer: stream in proj weight image (24.6KB) into B region
    if(last){
        #pragma unroll
        for(int m=0;m<6;m++){
            int id = tid + m*256;
            int ch = id >> 7;
            int rem = id & 127;
            int d = rem >> 6;
            int rem2 = rem & 63;
            int o = rem2 >> 1, s = rem2 & 1;
            uint32_t dst = sbase + BOFF + (uint32_t)ch*2048 + (uint32_t)d*1024
                         + (uint32_t)o*32 + (uint32_t)((s ^ ((o>>2)&1)) << 4);
            CP16(dst, (const uint4*)g_pr + id);
        }
        CP_COMMIT;
    }

    #pragma unroll
    for(int mt=0;mt<2;mt++)
        #pragma unroll
        for(int h=0;h<2;h++){
            float a = s1[mt][h], b2 = s2[mt][h];
            a  += __shfl_xor_sync(0xffffffffu, a, 1);
            a  += __shfl_xor_sync(0xffffffffu, a, 2);
            b2 += __shfl_xor_sync(0xffffffffu, b2, 1);
            b2 += __shfl_xor_sync(0xffffffffu, b2, 2);
            if(qi==0){
                int row = wm*32 + mt*16 + h*8 + q;
                red1[wn*64 + row] = a;
                red2[wn*64 + row] = b2;
            }
        }
    __syncthreads();
    if(tid < 64){
        float t1 = red1[tid] + red1[64+tid] + red1[128+tid] + red1[192+tid];
        float t2 = red2[tid] + red2[64+tid] + red2[128+tid] + red2[192+tid];
        float mu = t1*(1.0f/H);
        musm[tid] = mu;
        rssm[tid] = rsqrtf(t2*(1.0f/H) - mu*mu + 1e-5f);
    }
    __syncthreads();

    const float* lg = par + 192;
    const float* lb = par + 384;
    #pragma unroll
    for(int mt=0;mt<2;mt++)
        #pragma unroll
        for(int h=0;h<2;h++){
            int r = wm*32 + mt*16 + h*8 + q;
            float mu = musm[r], rs = rssm[r];
            long long grow = bt0 + r;
            float xa = 0.f;
            const float* ginrow = gin + grow*H;
            if(first) xa = x[((long long)b*2)*T + t0 + r];
            float* goutrow = gout + grow*H;
            int xr = (r>>2)&1;
            #pragma unroll
            for(int nt=0;nt<6;nt++){
                int col = wn*48 + nt*8 + qi*2;
                float v0 = acc[mt][nt][h*2], v1 = acc[mt][nt][h*2+1];
                float res0, res1;
                if(first){
                    res0 = __ldg(in_w + col)*xa   + __ldg(in_b + col);
                    res1 = __ldg(in_w + col+1)*xa + __ldg(in_b + col+1);
                } else {
                    float2 rv = *(const float2*)(ginrow + col);
                    res0 = rv.x; res1 = rv.y;
                }
                float o0 = gelu_fast((v0-mu)*rs*lg[col]   + lb[col])   + res0;
                float o1 = gelu_fast((v1-mu)*rs*lg[col+1] + lb[col+1]) + res1;
                if(!last){
                    *(float2*)(goutrow + col) = make_float2(o0, o1);
                } else {
                    // split final residual into A smem for the proj GEMM
                    uint32_t ph, pl;
                    split2(o0, o1, ph, pl);
                    uint32_t off = (uint32_t)(col>>4)*2048 + (uint32_t)r*32
                                 + (uint32_t)((((col>>3)&1) ^ xr) << 4)
                                 + (uint32_t)(col&7)*2;
                    *(uint32_t*)(smem + A_HI + off) = ph;
                    *(uint32_t*)(smem + A_LO + off) = pl;
                }
            }
        }

    if(!last) return;

    // ---------------- last layer: proj GEMM (64x32x192) ----------------
    CP_WAIT0;
    __syncthreads();   // proj image + split-A visible to all

    int wm2 = wid & 3, wn2 = wid >> 2;    // 4 warps in M (16 rows), 2 in N (16 cols)
    uint32_t a2Off, b2Off;
    {
        int row = wm2*16 + (g2&1)*8 + lr;
        a2Off = (uint32_t)row*32 + (uint32_t)(((g2>>1) ^ ((row>>2)&1)) << 4);
        int o = wn2*16 + (g2>>1)*8 + lr;
        b2Off = (uint32_t)o*32 + (uint32_t)(((g2&1) ^ ((o>>2)&1)) << 4);
    }
    float acc2[2][4];
    #pragma unroll
    for(int nt=0;nt<2;nt++)
        #pragma unroll
        for(int r2=0;r2<4;r2++) acc2[nt][r2] = 0.f;

    #pragma unroll 1
    for(int ch=0; ch<12; ch++){
        uint32_t aB  = sbase + A_HI + (uint32_t)ch*2048;
        uint32_t aBl = sbase + A_LO + (uint32_t)ch*2048;
        uint32_t bB  = sbase + BOFF + (uint32_t)ch*2048;
        uint32_t ah[4], al[4], bb[4];
        LDSM4(ah, aB  + a2Off);
        LDSM4(al, aBl + a2Off);
        LDSM4(bb, bB + b2Off);
        MMA16816(acc2[0], ah, bb[0], bb[1]);
        MMA16816(acc2[1], ah, bb[2], bb[3]);
        MMA16816(acc2[0], al, bb[0], bb[1]);
        MMA16816(acc2[1], al, bb[2], bb[3]);
        LDSM4(bb, bB + 1024 + b2Off);
        MMA16816(acc2[0], ah, bb[0], bb[1]);
        MMA16816(acc2[1], ah, bb[2], bb[3]);
    }

    float* Psm = (float*)(smem + PSM_OFF);   // [64][33]
    #pragma unroll
    for(int h=0;h<2;h++){
        int row = wm2*16 + h*8 + q;
        #pragma unroll
        for(int nt=0;nt<2;nt++){
            int col = wn2*16 + nt*8 + qi*2;
            Psm[row*33 + col]   = acc2[nt][h*2];
            Psm[row*33 + col+1] = acc2[nt][h*2+1];
        }
    }
    __syncthreads();

    // ---------------- spline math: tid<64, one row each ----------------
    float lv = 0.f;
    if(tid < 64){
        int t = t0 + tid;
        float mask = xmask[(long long)b*T + t];
        float p[NJ];
        #pragma unroll
        for(int j=0;j<NJ;j++) p[j] = (Psm[tid*33 + j] + __ldg(proj_b + j)) * mask;

        const float inv_dn = 0.07216878364870323f;   // 1/sqrt(192)

        float cwv[BINS+1], wsv[BINS];
        {
            float m = -1e30f;
            #pragma unroll
            for(int j=0;j<BINS;j++) m = fmaxf(m, p[j]);
            float e[BINS]; float ssum = 0.f;
            #pragma unroll
            for(int j=0;j<BINS;j++){ e[j] = __expf((p[j]-m)*inv_dn); ssum += e[j]; }
            float inv = 1.0f/ssum;
            float cum = 0.f;
            cwv[0] = -TAILV;
            #pragma unroll
            for(int j=0;j<BINS;j++){
                float wj = 1e-3f + 0.99f*e[j]*inv;
                cum += wj;
                cwv[j+1] = 2.0f*TAILV*cum - TAILV;
            }
            cwv[BINS] = TAILV;
            #pragma unroll
            for(int j=0;j<BINS;j++) wsv[j] = cwv[j+1]-cwv[j];
        }
        float chv[BINS+1], hsv[BINS];
        {
            float m = -1e30f;
            #pragma unroll
            for(int j=0;j<BINS;j++) m = fmaxf(m, p[BINS+j]);
            float e[BINS]; float ssum = 0.f;
            #pragma unroll
            for(int j=0;j<BINS;j++){ e[j] = __expf((p[BINS+j]-m)*inv_dn); ssum += e[j]; }
            float inv = 1.0f/ssum;
            float cum = 0.f;
            chv[0] = -TAILV;
            #pragma unroll
            for(int j=0;j<BINS;j++){
                float hj = 1e-3f + 0.99f*e[j]*inv;
                cum += hj;
                chv[j+1] = 2.0f*TAILV*cum - TAILV;
            }
            chv[BINS] = TAILV;
            #pragma unroll
            for(int j=0;j<BINS;j++) hsv[j] = chv[j+1]-chv[j];
        }
        float derv[BINS+1];
        derv[0] = 1.0f; derv[BINS] = 1.0f;
        #pragma unroll
        for(int k=1;k<BINS;k++){
            float u = p[2*BINS + k - 1];
            float sp = (u > 20.f) ? u : __logf(1.0f + __expf(u));
            derv[k] = 1e-3f + sp;
        }

        float xbv = x[((long long)b*2+1)*T + t];
        bool inside = (xbv >= -TAILV) && (xbv <= TAILV);
        float xc = fminf(fmaxf(xbv, -TAILV), TAILV);
        int idx = 0;
        #pragma unroll
        for(int j=0;j<BINS;j++) idx += (xc >= cwv[j]) ? 1 : 0;
        idx -= 1;
        idx = max(0, min(BINS-1, idx));

        float icw=0.f, ibw=1.f, ich=0.f, ih=1.f, dk=1.f, dk1=1.f;
        #pragma unroll
        for(int j=0;j<BINS;j++){
            bool sel = (idx==j);
            icw = sel ? cwv[j]   : icw;
            ibw = sel ? wsv[j]   : ibw;
            ich = sel ? chv[j]   : ich;
            ih  = sel ? hsv[j]   : ih;
            dk  = sel ? derv[j]  : dk;
            dk1 = sel ? derv[j+1]: dk1;
        }

        float idl = ih/ibw;
        float th  = (xc - icw)/ibw;
        float t1m = th*(1.0f - th);
        float num = ih*(idl*th*th + dk*t1m);
        float den = idl + (dk + dk1 - 2.0f*idl)*t1m;
        float outv = ich + num/den;
        float omt = 1.0f - th;
        float dnum = idl*idl*(dk1*th*th + 2.0f*idl*t1m + dk*omt*omt);
        float lad = __logf(dnum) - 2.0f*__logf(den);

        float xb2 = inside ? outv : xbv;
        lad = inside ? lad : 0.0f;

        float xav = x[((long long)b*2)*T + t];
        out[(long long)b*2*T + t]     = xav*mask;
        out[(long long)b*2*T + T + t] = xb2*mask;
        lv = lad*mask;
    }

    // logdet reduction: tid<64 -> warps 0,1
    if(wid < 2){
        #pragma unroll
        for(int o=16;o>0;o>>=1) lv += __shfl_xor_sync(0xffffffffu, lv, o);
        if(lane == 0) redL[wid] = lv;
    }
    __syncthreads();
    if(tid == 0)
        atomicAdd(out + (long long)B*2*T + b, redL[0] + redL[1]);
}

// ---------------------------------------------------------------------------
extern "C" void kernel_launch(void* const* d_in, const int* in_sizes, int n_in,
                              void* d_out, int out_size)
{
    const float* x      = (const float*)d_in[0];
    const float* xmask  = (const float*)d_in[1];
    const float* in_w   = (const float*)d_in[2];
    const float* in_b   = (const float*)d_in[3];
    const float* dw_w   = (const float*)d_in[4];
    const float* dw_b   = (const float*)d_in[5];
    const float* ln1_g  = (const float*)d_in[6];
    const float* ln1_b  = (const float*)d_in[7];
    const float* pw_w   = (const float*)d_in[8];
    const float* pw_b   = (const float*)d_in[9];
    const float* ln2_g  = (const float*)d_in[10];
    const float* ln2_b  = (const float*)d_in[11];
    const float* proj_w = (const float*)d_in[12];
    const float* proj_b = (const float*)d_in[13];
    float* out = (float*)d_out;

    cudaFuncSetAttribute(k_fused, cudaFuncAttributeMaxDynamicSharedMemorySize, FUSED_SMEM_BYTES);

    k_zero<<<1, 32>>>(out);
    k_zero<<<1, 32>>>(out);          // dup: aligns ncu -s 5 onto fused L2
    k_prep<<<(3*H*H + 255)/256, 256>>>(pw_w, proj_w, dw_w);
    int dil = 1;
    for(int L=0; L<3; L++){
        k_fused<<<BT/64, 256, FUSED_SMEM_BYTES>>>(L, dil, x, in_w, in_b, xmask,
            dw_b, ln1_g, ln1_b, pw_b, ln2_g, ln2_b, proj_b, out);
        dil *= 3;
    }
}

// round 12
// speedup vs baseline: 1.0942x; 1.0942x over previous
#include <cuda_runtime.h>
#include <cuda_bf16.h>
#include <math.h>
#include <stdint.h>

#define B 32
#define T 8192
#define H 192
#define BT (B*T)
#define BINS 10
#define TAILV 5.0f
#define NJ 29

// residual stream ping-pong buffers (f32), layout [b][t][c]
__device__ float g_x0[(size_t)BT*H];
__device__ float g_x1[(size_t)BT*H];
// chunk-ordered pw weight image: [layer][chunk12][dtype2][o192][seg2][8bf16]
__device__ __align__(16) __nv_bfloat16 g_wr[3*12*2*192*16];
// chunk-ordered proj weight image: [chunk12][dtype2][o32][seg2][8bf16]
__device__ __align__(16) __nv_bfloat16 g_pr[12*2*32*16];
// transposed depthwise weights: [layer][tap][c]
__device__ float g_dwt[3*3*192];

// fast gelu: v - v/(exp(2c(v+av^3))+1); tails exact, |err|<~2e-4 abs
__device__ __forceinline__ float gelu_fast(float v){
    float t2 = 1.5957691216057308f * fmaf(0.044715f*v, v*v, v);
    float e = __expf(t2);
    float r;
    asm("rcp.approx.f32 %0, %1;" : "=f"(r) : "f"(e + 1.0f));
    return fmaf(-v, r, v);
}

// split (y0,y1) into packed bf16x2 hi + lo parts
__device__ __forceinline__ void split2(float y0, float y1, uint32_t& ph, uint32_t& pl){
    uint32_t h;
    asm("cvt.rn.bf16x2.f32 %0, %1, %2;" : "=r"(h) : "f"(y1), "f"(y0));
    float h0 = __uint_as_float(h << 16);
    float h1 = __uint_as_float(h & 0xffff0000u);
    asm("cvt.rn.bf16x2.f32 %0, %1, %2;" : "=r"(pl) : "f"(y1 - h1), "f"(y0 - h0));
    ph = h;
}

__device__ __forceinline__ uint32_t smem_u32(const void* p){
    uint32_t a;
    asm("{ .reg .u64 t; cvta.to.shared.u64 t, %1; cvt.u32.u64 %0, t; }" : "=r"(a) : "l"(p));
    return a;
}

#define LDSM4(r, addr) \
    asm volatile("ldmatrix.sync.aligned.m8n8.x4.shared.b16 {%0,%1,%2,%3}, [%4];" \
        : "=r"((r)[0]),"=r"((r)[1]),"=r"((r)[2]),"=r"((r)[3]) : "r"(addr))

#define MMA16816(d, a, b0, b1) \
    asm volatile("mma.sync.aligned.m16n8k16.row.col.f32.bf16.bf16.f32 " \
        "{%0,%1,%2,%3},{%4,%5,%6,%7},{%8,%9},{%0,%1,%2,%3};" \
        : "+f"((d)[0]),"+f"((d)[1]),"+f"((d)[2]),"+f"((d)[3]) \
        : "r"((a)[0]),"r"((a)[1]),"r"((a)[2]),"r"((a)[3]), "r"(b0),"r"(b1))

#define CP16(dst, src) \
    asm volatile("cp.async.cg.shared.global [%0], [%1], 16;" :: "r"(dst), "l"(src))
#define CP_COMMIT asm volatile("cp.async.commit_group;" ::: "memory")
#define CP_WAIT2  asm volatile("cp.async.wait_group 2;" ::: "memory")
#define CP_WAIT1  asm volatile("cp.async.wait_group 1;" ::: "memory")
#define CP_WAIT0  asm volatile("cp.async.wait_group 0;" ::: "memory")

// ---------------------------------------------------------------------------
__global__ void k_zero(float* __restrict__ out){
    out[(long long)B*2*T + threadIdx.x] = 0.0f;
}

// prep: pw chunk image, proj chunk image, dw transpose
__global__ void k_prep(const float* __restrict__ pw_w,
                       const float* __restrict__ proj_w,
                       const float* __restrict__ dw_w)
{
    int i = blockIdx.x*256 + threadIdx.x;
    if (i < 3*H*H){
        int L = i / (H*H);
        int r = i - L*(H*H);
        int o = r / H, k = r - o*H;
        float w = pw_w[i];
        __nv_bfloat16 hb = __float2bfloat16(w);
        __nv_bfloat16 lb = __float2bfloat16(w - __bfloat162float(hb));
        int ch = k >> 4;
        int s  = (k >> 3) & 1;
        int j  = k & 7;
        size_t base = (((size_t)(L*12 + ch)*2)*192 + o)*16 + s*8 + j;
        g_wr[base]        = hb;
        g_wr[base + 3072] = lb;
    }
    if (i < 12*2*32*16){
        int ch = i >> 10;
        int rem = i & 1023;
        int d = rem >> 9;
        int rem2 = rem & 511;
        int o = rem2 >> 4;
        int s = (rem2 >> 3) & 1;
        int j = rem2 & 7;
        int k = ch*16 + s*8 + j;
        float w = (o < NJ) ? proj_w[o*H + k] : 0.0f;
        __nv_bfloat16 hb = __float2bfloat16(w);
        __nv_bfloat16 lb = __float2bfloat16(w - __bfloat162float(hb));
        g_pr[i] = d ? lb : hb;
    }
    if (i < 3*3*H){
        int L = i / (3*H);
        int rem = i - L*(3*H);
        int c = rem / 3, k = rem - c*3;
        g_dwt[L*(3*H) + k*H + c] = dw_w[i];
    }
}

// ---------------------------------------------------------------------------
// FUSED kernel (templated on FIRST/LAST): conv(dil)+LN1+gelu -> split-bf16
// GEMM (W streamed, 4-stage ring) -> bias+LN2+gelu+residual.
// LAST additionally: proj GEMM + RQ-spline + outputs + logdet, in-CTA.
#define A_HI    0
#define A_LO    24576
#define BOFF    49152
#define BSTG    12288
#define PSM_OFF (BOFF + 24576)
#define PAR_OFF (BOFF + 4*BSTG)        // 98304
#define RED_OFF (PAR_OFF + 2304)
#define FUSED_SMEM_BYTES (RED_OFF + 2592)

template<bool FIRST, bool LAST>
__global__ void __launch_bounds__(256,2) k_fused(int layer, int dil,
    const float* __restrict__ x,
    const float* __restrict__ in_w, const float* __restrict__ in_b,
    const float* __restrict__ xmask,
    const float* __restrict__ dw_b,
    const float* __restrict__ ln1_g, const float* __restrict__ ln1_b,
    const float* __restrict__ pw_b,
    const float* __restrict__ ln2_g, const float* __restrict__ ln2_b,
    const float* __restrict__ proj_b,
    float* __restrict__ out)
{
    extern __shared__ char smem[];
    uint32_t sbase = smem_u32(smem);
    int tid = threadIdx.x;
    int wid = tid >> 5, lane = tid & 31;
    int wm = wid & 1, wn = wid >> 1;          // 2 warps in M, 4 in N
    int q = lane >> 2, qi = lane & 3;
    long long bt0 = (long long)blockIdx.x * 64;
    int b  = (int)(bt0 >> 13);
    int t0 = (int)(bt0 & (T-1));
    const float* gin = LAST ? g_x1 : g_x0;
    float* gout = FIRST ? g_x0 : g_x1;

    uint32_t dstB[3];
    #pragma unroll
    for(int m=0;m<3;m++){
        int id = tid + m*256;
        int d = id / 384;
        int rem = id - d*384;
        int o = rem >> 1, s = rem & 1;
        dstB[m] = (uint32_t)d*6144 + (uint32_t)o*32
                + (uint32_t)((s ^ ((o>>2)&1)) << 4);
    }
    const uint4* wrp = (const uint4*)g_wr + (size_t)layer*9216 + tid;

#define ISSUE(cc, st) do { \
    uint32_t _bs = sbase + BOFF + (uint32_t)(st)*BSTG; \
    const uint4* _w = wrp + (cc)*768; \
    CP16(_bs + dstB[0], _w); \
    CP16(_bs + dstB[1], _w + 256); \
    CP16(_bs + dstB[2], _w + 512); \
    CP_COMMIT; \
} while(0)

    ISSUE(0, 0);
    ISSUE(1, 1);
    ISSUE(2, 2);

    float* par = (float*)(smem + PAR_OFF);
    if(tid < 192){
        par[tid]       = pw_b[layer*H + tid];
        par[192 + tid] = ln2_g[layer*H + tid];
        par[384 + tid] = ln2_b[layer*H + tid];
    }

    // ---------------- phase 1: conv + LN1 + gelu -> A smem ----------------
    {
        int c0 = lane*6;
        float w0[6], w1[6], w2[6], bbv[6], ggv[6], gbv[6];
        const float* wt = g_dwt + layer*(3*H);
        #pragma unroll
        for(int p=0;p<3;p++){
            float2 a = *(const float2*)(wt + c0 + p*2);
            w0[p*2]=a.x; w0[p*2+1]=a.y;
            float2 bq = *(const float2*)(wt + H + c0 + p*2);
            w1[p*2]=bq.x; w1[p*2+1]=bq.y;
            float2 cq = *(const float2*)(wt + 2*H + c0 + p*2);
            w2[p*2]=cq.x; w2[p*2+1]=cq.y;
            float2 d = *(const float2*)(dw_b + layer*H + c0 + p*2);
            bbv[p*2]=d.x; bbv[p*2+1]=d.y;
            float2 e = *(const float2*)(ln1_g + layer*H + c0 + p*2);
            ggv[p*2]=e.x; ggv[p*2+1]=e.y;
            float2 f = *(const float2*)(ln1_b + layer*H + c0 + p*2);
            gbv[p*2]=f.x; gbv[p*2+1]=f.y;
        }
        float iw[6], ib[6];
        if(FIRST){
            #pragma unroll
            for(int p=0;p<3;p++){
                float2 a = *(const float2*)(in_w + c0 + p*2);
                iw[p*2]=a.x; iw[p*2+1]=a.y;
                float2 bq = *(const float2*)(in_b + c0 + p*2);
                ib[p*2]=bq.x; ib[p*2+1]=bq.y;
            }
        }
        const float* mrow = xmask + (long long)b*T;
        const float* xrowa = x + ((long long)b*2)*T;

        #pragma unroll 1
        for(int rr=0; rr<8; rr++){
            int r = wid*8 + rr;
            long long grow = bt0 + r;
            int t = t0 + r;
            int tm = t - dil, tp = t + dil;
            bool hm = (tm >= 0), hp = (tp < T);
            float mm = hm ? mrow[tm] : 0.f;
            float m0 = mrow[t];
            float mp = hp ? mrow[tp] : 0.f;

            float xm[6], xz[6], xp[6];
            if(FIRST){
                float xam = hm ? xrowa[tm] : 0.f;
                float xa0 = xrowa[t];
                float xap = hp ? xrowa[tp] : 0.f;
                #pragma unroll
                for(int k=0;k<6;k++){
                    xm[k] = iw[k]*xam + ib[k];
                    xz[k] = iw[k]*xa0 + ib[k];
                    xp[k] = iw[k]*xap + ib[k];
                }
            } else {
                const float* base = gin + grow*H + c0;
                #pragma unroll
                for(int p=0;p<3;p++){
                    float2 a = *(const float2*)(base + p*2);
                    xz[p*2]=a.x; xz[p*2+1]=a.y;
                }
                if(hm){
                    const float* bmp = base - (long long)dil*H;
                    #pragma unroll
                    for(int p=0;p<3;p++){
                        float2 a = *(const float2*)(bmp + p*2);
                        xm[p*2]=a.x; xm[p*2+1]=a.y;
                    }
                } else {
                    #pragma unroll
                    for(int k=0;k<6;k++) xm[k]=0.f;
                }
                if(hp){
                    const float* bpp = base + (long long)dil*H;
                    #pragma unroll
                    for(int p=0;p<3;p++){
                        float2 a = *(const float2*)(bpp + p*2);
                        xp[p*2]=a.x; xp[p*2+1]=a.y;
                    }
                } else {
                    #pragma unroll
                    for(int k=0;k<6;k++) xp[k]=0.f;
                }
            }

            float v[6];
            float s=0.f, sq=0.f;
            #pragma unroll
            for(int k=0;k<6;k++){
                float rv = w0[k]*(xm[k]*mm) + w1[k]*(xz[k]*m0) + w2[k]*(xp[k]*mp) + bbv[k];
                v[k]=rv; s+=rv; sq+=rv*rv;
            }
            #pragma unroll
            for(int o=16;o>0;o>>=1){
                s  += __shfl_xor_sync(0xffffffffu, s,  o);
                sq += __shfl_xor_sync(0xffffffffu, sq, o);
            }
            float mu = s*(1.0f/H);
            float rs = rsqrtf(sq*(1.0f/H) - mu*mu + 1e-5f);

            int xr = (r>>2)&1;
            #pragma unroll
            for(int p=0;p<3;p++){
                float y0 = gelu_fast((v[p*2]  -mu)*rs*ggv[p*2]   + gbv[p*2]);
                float y1 = gelu_fast((v[p*2+1]-mu)*rs*ggv[p*2+1] + gbv[p*2+1]);
                uint32_t ph, pl;
                split2(y0, y1, ph, pl);
                int c = c0 + 2*p;
                uint32_t off = (uint32_t)(c>>4)*2048 + (uint32_t)r*32
                             + (uint32_t)((((c>>3)&1) ^ xr) << 4) + (uint32_t)(c&7)*2;
                *(uint32_t*)(smem + A_HI + off) = ph;
                *(uint32_t*)(smem + A_LO + off) = pl;
            }
        }
    }

    // ---------------- phase 2: k-loop (12 chunks of k=16) ----------------
    int g2 = lane >> 3, lr = lane & 7;
    uint32_t aOff[2];
    #pragma unroll
    for(int mt=0;mt<2;mt++){
        int row = wm*32 + mt*16 + (g2&1)*8 + lr;
        aOff[mt] = (uint32_t)row*32 + (uint32_t)(((g2>>1) ^ ((row>>2)&1)) << 4);
    }
    uint32_t bOff[3];
    #pragma unroll
    for(int i=0;i<3;i++){
        int o = wn*48 + i*16 + (g2>>1)*8 + lr;
        bOff[i] = (uint32_t)o*32 + (uint32_t)(((g2&1) ^ ((o>>2)&1)) << 4);
    }

    float acc[2][6][4];
    #pragma unroll
    for(int mt=0;mt<2;mt++)
        #pragma unroll
        for(int nt=0;nt<6;nt++)
            #pragma unroll
            for(int r2=0;r2<4;r2++) acc[mt][nt][r2] = 0.f;

#define PASS(AH, BB) \
    _Pragma("unroll") \
    for(int mt=0;mt<2;mt++){ \
        _Pragma("unroll") \
        for(int i=0;i<3;i++){ \
            MMA16816(acc[mt][2*i],   AH[mt], BB[i][0], BB[i][1]); \
            MMA16816(acc[mt][2*i+1], AH[mt], BB[i][2], BB[i][3]); \
        } \
    }

    #pragma unroll 1
    for(int c=0;c<12;c++){
        if(c<10){ CP_WAIT2; } else if(c==10){ CP_WAIT1; } else { CP_WAIT0; }
        __syncthreads();
        if(c<9) ISSUE(c+3, (c+3)&3);
        uint32_t aB  = sbase + A_HI + (uint32_t)c*2048;
        uint32_t aBl = sbase + A_LO + (uint32_t)c*2048;
        uint32_t bB  = sbase + BOFF + (uint32_t)(c&3)*BSTG;

        uint32_t ah[2][4], al[2][4], bb[3][4];
        LDSM4(ah[0], aB  + aOff[0]);
        LDSM4(ah[1], aB  + aOff[1]);
        LDSM4(al[0], aBl + aOff[0]);
        LDSM4(al[1], aBl + aOff[1]);
        #pragma unroll
        for(int i=0;i<3;i++) LDSM4(bb[i], bB + bOff[i]);
        PASS(ah, bb)
        PASS(al, bb)
        #pragma unroll
        for(int i=0;i<3;i++) LDSM4(bb[i], bB + 6144 + bOff[i]);
        PASS(ah, bb)
    }
#undef PASS

    // ---------------- epilogue: bias + LN2 + gelu + residual ----------------
    float* red1 = (float*)(smem + RED_OFF);
    float* red2 = red1 + 256;
    float* musm = red1 + 512;
    float* rssm = red1 + 576;
    float* redL = red1 + 640;

    float s1[2][2] = {{0.f,0.f},{0.f,0.f}};
    float s2[2][2] = {{0.f,0.f},{0.f,0.f}};
    #pragma unroll
    for(int mt=0;mt<2;mt++)
        #pragma unroll
        for(int nt=0;nt<6;nt++){
            int col = wn*48 + nt*8 + qi*2;
            float b0 = par[col], b1 = par[col+1];
            acc[mt][nt][0] += b0; acc[mt][nt][1] += b1;
            acc[mt][nt][2] += b0; acc[mt][nt][3] += b1;
            #pragma unroll
            for(int h=0;h<2;h++){
                float v0 = acc[mt][nt][h*2], v1 = acc[mt][nt][h*2+1];
                s1[mt][h] += v0 + v1;
                s2[mt][h] += v0*v0 + v1*v1;
            }
        }
    __syncthreads();   // all warps past mainloop: A and B smem regions dead

    if(LAST){
        // stream in proj weight image (24.6KB) into B region
        #pragma unroll
        for(int m=0;m<6;m++){
            int id = tid + m*256;
            int ch = id >> 7;
            int rem = id & 127;
            int d = rem >> 6;
            int rem2 = rem & 63;
            int o = rem2 >> 1, s = rem2 & 1;
            uint32_t dst = sbase + BOFF + (uint32_t)ch*2048 + (uint32_t)d*1024
                         + (uint32_t)o*32 + (uint32_t)((s ^ ((o>>2)&1)) << 4);
            CP16(dst, (const uint4*)g_pr + id);
        }
        CP_COMMIT;
    }

    #pragma unroll
    for(int mt=0;mt<2;mt++)
        #pragma unroll
        for(int h=0;h<2;h++){
            float a = s1[mt][h], b2 = s2[mt][h];
            a  += __shfl_xor_sync(0xffffffffu, a, 1);
            a  += __shfl_xor_sync(0xffffffffu, a, 2);
            b2 += __shfl_xor_sync(0xffffffffu, b2, 1);
            b2 += __shfl_xor_sync(0xffffffffu, b2, 2);
            if(qi==0){
                int row = wm*32 + mt*16 + h*8 + q;
                red1[wn*64 + row] = a;
                red2[wn*64 + row] = b2;
            }
        }
    __syncthreads();
    if(tid < 64){
        float t1 = red1[tid] + red1[64+tid] + red1[128+tid] + red1[192+tid];
        float t2 = red2[tid] + red2[64+tid] + red2[128+tid] + red2[192+tid];
        float mu = t1*(1.0f/H);
        musm[tid] = mu;
        rssm[tid] = rsqrtf(t2*(1.0f/H) - mu*mu + 1e-5f);
    }
    __syncthreads();

    const float* lg = par + 192;
    const float* lb = par + 384;
    #pragma unroll
    for(int mt=0;mt<2;mt++)
        #pragma unroll
        for(int h=0;h<2;h++){
            int r = wm*32 + mt*16 + h*8 + q;
            float mu = musm[r], rs = rssm[r];
            long long grow = bt0 + r;
            float xa = 0.f;
            const float* ginrow = gin + grow*H;
            if(FIRST) xa = x[((long long)b*2)*T + t0 + r];
            float* goutrow = gout + grow*H;
            int xr = (r>>2)&1;
            #pragma unroll
            for(int nt=0;nt<6;nt++){
                int col = wn*48 + nt*8 + qi*2;
                float v0 = acc[mt][nt][h*2], v1 = acc[mt][nt][h*2+1];
                float res0, res1;
                if(FIRST){
                    res0 = __ldg(in_w + col)*xa   + __ldg(in_b + col);
                    res1 = __ldg(in_w + col+1)*xa + __ldg(in_b + col+1);
                } else {
                    float2 rv = *(const float2*)(ginrow + col);
                    res0 = rv.x; res1 = rv.y;
                }
                float o0 = gelu_fast((v0-mu)*rs*lg[col]   + lb[col])   + res0;
                float o1 = gelu_fast((v1-mu)*rs*lg[col+1] + lb[col+1]) + res1;
                if(!LAST){
                    *(float2*)(goutrow + col) = make_float2(o0, o1);
                } else {
                    uint32_t ph, pl;
                    split2(o0, o1, ph, pl);
                    uint32_t off = (uint32_t)(col>>4)*2048 + (uint32_t)r*32
                                 + (uint32_t)((((col>>3)&1) ^ xr) << 4)
                                 + (uint32_t)(col&7)*2;
                    *(uint32_t*)(smem + A_HI + off) = ph;
                    *(uint32_t*)(smem + A_LO + off) = pl;
                }
            }
        }

    if(!LAST) return;

    // ---------------- last layer: proj GEMM (64x32x192) ----------------
    CP_WAIT0;
    __syncthreads();

    int wm2 = wid & 3, wn2 = wid >> 2;
    uint32_t a2Off, b2Off;
    {
        int row = wm2*16 + (g2&1)*8 + lr;
        a2Off = (uint32_t)row*32 + (uint32_t)(((g2>>1) ^ ((row>>2)&1)) << 4);
        int o = wn2*16 + (g2>>1)*8 + lr;
        b2Off = (uint32_t)o*32 + (uint32_t)(((g2&1) ^ ((o>>2)&1)) << 4);
    }
    float acc2[2][4];
    #pragma unroll
    for(int nt=0;nt<2;nt++)
        #pragma unroll
        for(int r2=0;r2<4;r2++) acc2[nt][r2] = 0.f;

    #pragma unroll 1
    for(int ch=0; ch<12; ch++){
        uint32_t aB  = sbase + A_HI + (uint32_t)ch*2048;
        uint32_t aBl = sbase + A_LO + (uint32_t)ch*2048;
        uint32_t bB  = sbase + BOFF + (uint32_t)ch*2048;
        uint32_t ah[4], al[4], bb[4];
        LDSM4(ah, aB  + a2Off);
        LDSM4(al, aBl + a2Off);
        LDSM4(bb, bB + b2Off);
        MMA16816(acc2[0], ah, bb[0], bb[1]);
        MMA16816(acc2[1], ah, bb[2], bb[3]);
        MMA16816(acc2[0], al, bb[0], bb[1]);
        MMA16816(acc2[1], al, bb[2], bb[3]);
        LDSM4(bb, bB + 1024 + b2Off);
        MMA16816(acc2[0], ah, bb[0], bb[1]);
        MMA16816(acc2[1], ah, bb[2], bb[3]);
    }

    float* Psm = (float*)(smem + PSM_OFF);
    #pragma unroll
    for(int h=0;h<2;h++){
        int row = wm2*16 + h*8 + q;
        #pragma unroll
        for(int nt=0;nt<2;nt++){
            int col = wn2*16 + nt*8 + qi*2;
            Psm[row*33 + col]   = acc2[nt][h*2];
            Psm[row*33 + col+1] = acc2[nt][h*2+1];
        }
    }
    __syncthreads();

    // ---------------- spline math: tid<64, one row each ----------------
    float lv = 0.f;
    if(tid < 64){
        int t = t0 + tid;
        float mask = xmask[(long long)b*T + t];
        float p[NJ];
        #pragma unroll
        for(int j=0;j<NJ;j++) p[j] = (Psm[tid*33 + j] + __ldg(proj_b + j)) * mask;

        const float inv_dn = 0.07216878364870323f;

        float cwv[BINS+1], wsv[BINS];
        {
            float m = -1e30f;
            #pragma unroll
            for(int j=0;j<BINS;j++) m = fmaxf(m, p[j]);
            float e[BINS]; float ssum = 0.f;
            #pragma unroll
            for(int j=0;j<BINS;j++){ e[j] = __expf((p[j]-m)*inv_dn); ssum += e[j]; }
            float inv = 1.0f/ssum;
            float cum = 0.f;
            cwv[0] = -TAILV;
            #pragma unroll
            for(int j=0;j<BINS;j++){
                float wj = 1e-3f + 0.99f*e[j]*inv;
                cum += wj;
                cwv[j+1] = 2.0f*TAILV*cum - TAILV;
            }
            cwv[BINS] = TAILV;
            #pragma unroll
            for(int j=0;j<BINS;j++) wsv[j] = cwv[j+1]-cwv[j];
        }
        float chv[BINS+1], hsv[BINS];
        {
            float m = -1e30f;
            #pragma unroll
            for(int j=0;j<BINS;j++) m = fmaxf(m, p[BINS+j]);
            float e[BINS]; float ssum = 0.f;
            #pragma unroll
            for(int j=0;j<BINS;j++){ e[j] = __expf((p[BINS+j]-m)*inv_dn); ssum += e[j]; }
            float inv = 1.0f/ssum;
            float cum = 0.f;
            chv[0] = -TAILV;
            #pragma unroll
            for(int j=0;j<BINS;j++){
                float hj = 1e-3f + 0.99f*e[j]*inv;
                cum += hj;
                chv[j+1] = 2.0f*TAILV*cum - TAILV;
            }
            chv[BINS] = TAILV;
            #pragma unroll
            for(int j=0;j<BINS;j++) hsv[j] = chv[j+1]-chv[j];
        }
        float derv[BINS+1];
        derv[0] = 1.0f; derv[BINS] = 1.0f;
        #pragma unroll
        for(int k=1;k<BINS;k++){
            float u = p[2*BINS + k - 1];
            float sp = (u > 20.f) ? u : __logf(1.0f + __expf(u));
            derv[k] = 1e-3f + sp;
        }

        float xbv = x[((long long)b*2+1)*T + t];
        bool inside = (xbv >= -TAILV) && (xbv <= TAILV);
        float xc = fminf(fmaxf(xbv, -TAILV), TAILV);
        int idx = 0;
        #pragma unroll
        for(int j=0;j<BINS;j++) idx += (xc >= cwv[j]) ? 1 : 0;
        idx -= 1;
        idx = max(0, min(BINS-1, idx));

        float icw=0.f, ibw=1.f, ich=0.f, ih=1.f, dk=1.f, dk1=1.f;
        #pragma unroll
        for(int j=0;j<BINS;j++){
            bool sel = (idx==j);
            icw = sel ? cwv[j]   : icw;
            ibw = sel ? wsv[j]   : ibw;
            ich = sel ? chv[j]   : ich;
            ih  = sel ? hsv[j]   : ih;
            dk  = sel ? derv[j]  : dk;
            dk1 = sel ? derv[j+1]: dk1;
        }

        float idl = ih/ibw;
        float th  = (xc - icw)/ibw;
        float t1m = th*(1.0f - th);
        float num = ih*(idl*th*th + dk*t1m);
        float den = idl + (dk + dk1 - 2.0f*idl)*t1m;
        float outv = ich + num/den;
        float omt = 1.0f - th;
        float dnum = idl*idl*(dk1*th*th + 2.0f*idl*t1m + dk*omt*omt);
        float lad = __logf(dnum) - 2.0f*__logf(den);

        float xb2 = inside ? outv : xbv;
        lad = inside ? lad : 0.0f;

        float xav = x[((long long)b*2)*T + t];
        out[(long long)b*2*T + t]     = xav*mask;
        out[(long long)b*2*T + T + t] = xb2*mask;
        lv = lad*mask;
    }

    if(wid < 2){
        #pragma unroll
        for(int o=16;o>0;o>>=1) lv += __shfl_xor_sync(0xffffffffu, lv, o);
        if(lane == 0) redL[wid] = lv;
    }
    __syncthreads();
    if(tid == 0)
        atomicAdd(out + (long long)B*2*T + b, redL[0] + redL[1]);
}

// ---------------------------------------------------------------------------
extern "C" void kernel_launch(void* const* d_in, const int* in_sizes, int n_in,
                              void* d_out, int out_size)
{
    const float* x      = (const float*)d_in[0];
    const float* xmask  = (const float*)d_in[1];
    const float* in_w   = (const float*)d_in[2];
    const float* in_b   = (const float*)d_in[3];
    const float* dw_w   = (const float*)d_in[4];
    const float* dw_b   = (const float*)d_in[5];
    const float* pw_w   = (const float*)d_in[8];
    const float* pw_b   = (const float*)d_in[9];
    const float* ln1_g  = (const float*)d_in[6];
    const float* ln1_b  = (const float*)d_in[7];
    const float* ln2_g  = (const float*)d_in[10];
    const float* ln2_b  = (const float*)d_in[11];
    const float* proj_w = (const float*)d_in[12];
    const float* proj_b = (const float*)d_in[13];
    float* out = (float*)d_out;

    cudaFuncSetAttribute(k_fused<true,false>,  cudaFuncAttributeMaxDynamicSharedMemorySize, FUSED_SMEM_BYTES);
    cudaFuncSetAttribute(k_fused<false,false>, cudaFuncAttributeMaxDynamicSharedMemorySize, FUSED_SMEM_BYTES);
    cudaFuncSetAttribute(k_fused<false,true>,  cudaFuncAttributeMaxDynamicSharedMemorySize, FUSED_SMEM_BYTES);

    k_zero<<<1, 32>>>(out);
    k_zero<<<1, 32>>>(out);
    k_zero<<<1, 32>>>(out);          // 3 dups: ncu -s 5 lands on fused L1
    k_prep<<<(3*H*H + 255)/256, 256>>>(pw_w, proj_w, dw_w);
    k_fused<true,false><<<BT/64, 256, FUSED_SMEM_BYTES>>>(0, 1, x, in_w, in_b, xmask,
        dw_b, ln1_g, ln1_b, pw_b, ln2_g, ln2_b, proj_b, out);
    k_fused<false,false><<<BT/64, 256, FUSED_SMEM_BYTES>>>(1, 3, x, in_w, in_b, xmask,
        dw_b, ln1_g, ln1_b, pw_b, ln2_g, ln2_b, proj_b, out);
    k_fused<false,true><<<BT/64, 256, FUSED_SMEM_BYTES>>>(2, 9, x, in_w, in_b, xmask,
        dw_b, ln1_g, ln1_b, pw_b, ln2_g, ln2_b, proj_b, out);
}

// round 14
// speedup vs baseline: 1.1331x; 1.0355x over previous
#include <cuda_runtime.h>
#include <cuda_bf16.h>
#include <math.h>
#include <stdint.h>

#define B 32
#define T 8192
#define H 192
#define BT (B*T)
#define BINS 10
#define TAILV 5.0f
#define NJ 29

// residual stream ping-pong buffers (f32), layout [b][t][c]
__device__ float g_x0[(size_t)BT*H];
__device__ float g_x1[(size_t)BT*H];
// chunk-ordered pw weight image: [layer][chunk12][dtype2][o192][seg2][8bf16]
__device__ __align__(16) __nv_bfloat16 g_wr[3*12*2*192*16];
// chunk-ordered proj weight image: [chunk12][dtype2][o32][seg2][8bf16]
__device__ __align__(16) __nv_bfloat16 g_pr[12*2*32*16];
// transposed depthwise weights: [layer][tap][c]
__device__ float g_dwt[3*3*192];

// fast gelu: v - v/(exp(2c(v+av^3))+1); tails exact, |err|<~2e-4 abs
__device__ __forceinline__ float gelu_fast(float v){
    float t2 = 1.5957691216057308f * fmaf(0.044715f*v, v*v, v);
    float e = __expf(t2);
    float r;
    asm("rcp.approx.f32 %0, %1;" : "=f"(r) : "f"(e + 1.0f));
    return fmaf(-v, r, v);
}

// split (y0,y1) into packed bf16x2 hi + lo parts
__device__ __forceinline__ void split2(float y0, float y1, uint32_t& ph, uint32_t& pl){
    uint32_t h;
    asm("cvt.rn.bf16x2.f32 %0, %1, %2;" : "=r"(h) : "f"(y1), "f"(y0));
    float h0 = __uint_as_float(h << 16);
    float h1 = __uint_as_float(h & 0xffff0000u);
    asm("cvt.rn.bf16x2.f32 %0, %1, %2;" : "=r"(pl) : "f"(y1 - h1), "f"(y0 - h0));
    ph = h;
}

__device__ __forceinline__ uint32_t smem_u32(const void* p){
    uint32_t a;
    asm("{ .reg .u64 t; cvta.to.shared.u64 t, %1; cvt.u32.u64 %0, t; }" : "=r"(a) : "l"(p));
    return a;
}

#define LDSM4(r, addr) \
    asm volatile("ldmatrix.sync.aligned.m8n8.x4.shared.b16 {%0,%1,%2,%3}, [%4];" \
        : "=r"((r)[0]),"=r"((r)[1]),"=r"((r)[2]),"=r"((r)[3]) : "r"(addr))

#define MMA16816(d, a, b0, b1) \
    asm volatile("mma.sync.aligned.m16n8k16.row.col.f32.bf16.bf16.f32 " \
        "{%0,%1,%2,%3},{%4,%5,%6,%7},{%8,%9},{%0,%1,%2,%3};" \
        : "+f"((d)[0]),"+f"((d)[1]),"+f"((d)[2]),"+f"((d)[3]) \
        : "r"((a)[0]),"r"((a)[1]),"r"((a)[2]),"r"((a)[3]), "r"(b0),"r"(b1))

#define CP16(dst, src) \
    asm volatile("cp.async.cg.shared.global [%0], [%1], 16;" :: "r"(dst), "l"(src))
#define CP_COMMIT asm volatile("cp.async.commit_group;" ::: "memory")
#define CP_WAIT2  asm volatile("cp.async.wait_group 2;" ::: "memory")
#define CP_WAIT1  asm volatile("cp.async.wait_group 1;" ::: "memory")
#define CP_WAIT0  asm volatile("cp.async.wait_group 0;" ::: "memory")

// ---------------------------------------------------------------------------
__global__ void k_zero(float* __restrict__ out){
    out[(long long)B*2*T + threadIdx.x] = 0.0f;
}

// prep: pw chunk image, proj chunk image, dw transpose
__global__ void k_prep(const float* __restrict__ pw_w,
                       const float* __restrict__ proj_w,
                       const float* __restrict__ dw_w)
{
    int i = blockIdx.x*256 + threadIdx.x;
    if (i < 3*H*H){
        int L = i / (H*H);
        int r = i - L*(H*H);
        int o = r / H, k = r - o*H;
        float w = pw_w[i];
        __nv_bfloat16 hb = __float2bfloat16(w);
        __nv_bfloat16 lb = __float2bfloat16(w - __bfloat162float(hb));
        int ch = k >> 4;
        int s  = (k >> 3) & 1;
        int j  = k & 7;
        size_t base = (((size_t)(L*12 + ch)*2)*192 + o)*16 + s*8 + j;
        g_wr[base]        = hb;
        g_wr[base + 3072] = lb;
    }
    if (i < 12*2*32*16){
        int ch = i >> 10;
        int rem = i & 1023;
        int d = rem >> 9;
        int rem2 = rem & 511;
        int o = rem2 >> 4;
        int s = (rem2 >> 3) & 1;
        int j = rem2 & 7;
        int k = ch*16 + s*8 + j;
        float w = (o < NJ) ? proj_w[o*H + k] : 0.0f;
        __nv_bfloat16 hb = __float2bfloat16(w);
        __nv_bfloat16 lb = __float2bfloat16(w - __bfloat162float(hb));
        g_pr[i] = d ? lb : hb;
    }
    if (i < 3*3*H){
        int L = i / (3*H);
        int rem = i - L*(3*H);
        int c = rem / 3, k = rem - c*3;
        g_dwt[L*(3*H) + k*H + c] = dw_w[i];
    }
}

// ---------------------------------------------------------------------------
// FUSED kernel (templated on FIRST/LAST): conv(dil)+LN1+gelu -> split-bf16
// GEMM (W streamed, 4-stage ring, 1 chunk/barrier — race-free schedule) ->
// bias+LN2+gelu+residual. LAST adds: proj GEMM + RQ-spline + logdet, in-CTA.
#define A_HI    0
#define A_LO    24576
#define BOFF    49152
#define BSTG    12288
#define PSM_OFF (BOFF + 24576)
#define PAR_OFF (BOFF + 4*BSTG)        // 98304
#define RED_OFF (PAR_OFF + 2304)
#define FUSED_SMEM_BYTES (RED_OFF + 2592)

template<bool FIRST, bool LAST>
__global__ void __launch_bounds__(256,2) k_fused(int layer, int dil,
    const float* __restrict__ x,
    const float* __restrict__ in_w, const float* __restrict__ in_b,
    const float* __restrict__ xmask,
    const float* __restrict__ dw_b,
    const float* __restrict__ ln1_g, const float* __restrict__ ln1_b,
    const float* __restrict__ pw_b,
    const float* __restrict__ ln2_g, const float* __restrict__ ln2_b,
    const float* __restrict__ proj_b,
    float* __restrict__ out)
{
    extern __shared__ char smem[];
    uint32_t sbase = smem_u32(smem);
    int tid = threadIdx.x;
    int wid = tid >> 5, lane = tid & 31;
    int wm = wid & 1, wn = wid >> 1;          // 2 warps in M, 4 in N
    int q = lane >> 2, qi = lane & 3;
    long long bt0 = (long long)blockIdx.x * 64;
    int b  = (int)(bt0 >> 13);
    int t0 = (int)(bt0 & (T-1));
    const float* gin = LAST ? g_x1 : g_x0;
    float* gout = FIRST ? g_x0 : g_x1;

    uint32_t dstB[3];
    #pragma unroll
    for(int m=0;m<3;m++){
        int id = tid + m*256;
        int d = id / 384;
        int rem = id - d*384;
        int o = rem >> 1, s = rem & 1;
        dstB[m] = (uint32_t)d*6144 + (uint32_t)o*32
                + (uint32_t)((s ^ ((o>>2)&1)) << 4);
    }
    const uint4* wrp = (const uint4*)g_wr + (size_t)layer*9216 + tid;

#define ISSUE(cc, st) do { \
    uint32_t _bs = sbase + BOFF + (uint32_t)(st)*BSTG; \
    const uint4* _w = wrp + (cc)*768; \
    CP16(_bs + dstB[0], _w); \
    CP16(_bs + dstB[1], _w + 256); \
    CP16(_bs + dstB[2], _w + 512); \
    CP_COMMIT; \
} while(0)

    ISSUE(0, 0);
    ISSUE(1, 1);
    ISSUE(2, 2);

    float* par = (float*)(smem + PAR_OFF);
    if(tid < 192){
        par[tid]       = pw_b[layer*H + tid];
        par[192 + tid] = ln2_g[layer*H + tid];
        par[384 + tid] = ln2_b[layer*H + tid];
    }

    // ---------------- phase 1: conv + LN1 + gelu -> A smem ----------------
    {
        int c0 = lane*6;
        float w0[6], w1[6], w2[6], bbv[6], ggv[6], gbv[6];
        const float* wt = g_dwt + layer*(3*H);
        #pragma unroll
        for(int p=0;p<3;p++){
            float2 a = *(const float2*)(wt + c0 + p*2);
            w0[p*2]=a.x; w0[p*2+1]=a.y;
            float2 bq = *(const float2*)(wt + H + c0 + p*2);
            w1[p*2]=bq.x; w1[p*2+1]=bq.y;
            float2 cq = *(const float2*)(wt + 2*H + c0 + p*2);
            w2[p*2]=cq.x; w2[p*2+1]=cq.y;
            float2 d = *(const float2*)(dw_b + layer*H + c0 + p*2);
            bbv[p*2]=d.x; bbv[p*2+1]=d.y;
            float2 e = *(const float2*)(ln1_g + layer*H + c0 + p*2);
            ggv[p*2]=e.x; ggv[p*2+1]=e.y;
            float2 f = *(const float2*)(ln1_b + layer*H + c0 + p*2);
            gbv[p*2]=f.x; gbv[p*2+1]=f.y;
        }
        float iw[6], ib[6];
        if(FIRST){
            #pragma unroll
            for(int p=0;p<3;p++){
                float2 a = *(const float2*)(in_w + c0 + p*2);
                iw[p*2]=a.x; iw[p*2+1]=a.y;
                float2 bq = *(const float2*)(in_b + c0 + p*2);
                ib[p*2]=bq.x; ib[p*2+1]=bq.y;
            }
        }
        const float* mrow = xmask + (long long)b*T;
        const float* xrowa = x + ((long long)b*2)*T;

        #pragma unroll 2
        for(int rr=0; rr<8; rr++){
            int r = wid*8 + rr;
            long long grow = bt0 + r;
            int t = t0 + r;
            int tm = t - dil, tp = t + dil;
            bool hm = (tm >= 0), hp = (tp < T);
            float mm = hm ? mrow[tm] : 0.f;
            float m0 = mrow[t];
            float mp = hp ? mrow[tp] : 0.f;

            float xm[6], xz[6], xp[6];
            if(FIRST){
                float xam = hm ? xrowa[tm] : 0.f;
                float xa0 = xrowa[t];
                float xap = hp ? xrowa[tp] : 0.f;
                #pragma unroll
                for(int k=0;k<6;k++){
                    xm[k] = iw[k]*xam + ib[k];
                    xz[k] = iw[k]*xa0 + ib[k];
                    xp[k] = iw[k]*xap + ib[k];
                }
            } else {
                const float* base = gin + grow*H + c0;
                #pragma unroll
                for(int p=0;p<3;p++){
                    float2 a = *(const float2*)(base + p*2);
                    xz[p*2]=a.x; xz[p*2+1]=a.y;
                }
                if(hm){
                    const float* bmp = base - (long long)dil*H;
                    #pragma unroll
                    for(int p=0;p<3;p++){
                        float2 a = *(const float2*)(bmp + p*2);
                        xm[p*2]=a.x; xm[p*2+1]=a.y;
                    }
                } else {
                    #pragma unroll
                    for(int k=0;k<6;k++) xm[k]=0.f;
                }
                if(hp){
                    const float* bpp = base + (long long)dil*H;
                    #pragma unroll
                    for(int p=0;p<3;p++){
                        float2 a = *(const float2*)(bpp + p*2);
                        xp[p*2]=a.x; xp[p*2+1]=a.y;
                    }
                } else {
                    #pragma unroll
                    for(int k=0;k<6;k++) xp[k]=0.f;
                }
            }

            float v[6];
            float s=0.f, sq=0.f;
            #pragma unroll
            for(int k=0;k<6;k++){
                float rv = w0[k]*(xm[k]*mm) + w1[k]*(xz[k]*m0) + w2[k]*(xp[k]*mp) + bbv[k];
                v[k]=rv; s+=rv; sq+=rv*rv;
            }
            #pragma unroll
            for(int o=16;o>0;o>>=1){
                s  += __shfl_xor_sync(0xffffffffu, s,  o);
                sq += __shfl_xor_sync(0xffffffffu, sq, o);
            }
            float mu = s*(1.0f/H);
            float rs = rsqrtf(sq*(1.0f/H) - mu*mu + 1e-5f);

            int xr = (r>>2)&1;
            #pragma unroll
            for(int p=0;p<3;p++){
                float y0 = gelu_fast((v[p*2]  -mu)*rs*ggv[p*2]   + gbv[p*2]);
                float y1 = gelu_fast((v[p*2+1]-mu)*rs*ggv[p*2+1] + gbv[p*2+1]);
                uint32_t ph, pl;
                split2(y0, y1, ph, pl);
                int c = c0 + 2*p;
                uint32_t off = (uint32_t)(c>>4)*2048 + (uint32_t)r*32
                             + (uint32_t)((((c>>3)&1) ^ xr) << 4) + (uint32_t)(c&7)*2;
                *(uint32_t*)(smem + A_HI + off) = ph;
                *(uint32_t*)(smem + A_LO + off) = pl;
            }
        }
    }

    // ---------------- phase 2: k-loop (12 chunks of k=16) ----------------
    int g2 = lane >> 3, lr = lane & 7;
    uint32_t aOff[2];
    #pragma unroll
    for(int mt=0;mt<2;mt++){
        int row = wm*32 + mt*16 + (g2&1)*8 + lr;
        aOff[mt] = (uint32_t)row*32 + (uint32_t)(((g2>>1) ^ ((row>>2)&1)) << 4);
    }
    uint32_t bOff[3];
    #pragma unroll
    for(int i=0;i<3;i++){
        int o = wn*48 + i*16 + (g2>>1)*8 + lr;
        bOff[i] = (uint32_t)o*32 + (uint32_t)(((g2&1) ^ ((o>>2)&1)) << 4);
    }

    float acc[2][6][4];
    #pragma unroll
    for(int mt=0;mt<2;mt++)
        #pragma unroll
        for(int nt=0;nt<6;nt++)
            #pragma unroll
            for(int r2=0;r2<4;r2++) acc[mt][nt][r2] = 0.f;

#define PASS(AH, BB) \
    _Pragma("unroll") \
    for(int mt=0;mt<2;mt++){ \
        _Pragma("unroll") \
        for(int i=0;i<3;i++){ \
            MMA16816(acc[mt][2*i],   AH[mt], BB[i][0], BB[i][1]); \
            MMA16816(acc[mt][2*i+1], AH[mt], BB[i][2], BB[i][3]); \
        } \
    }

    #pragma unroll 1
    for(int c=0;c<12;c++){
        if(c<10){ CP_WAIT2; } else if(c==10){ CP_WAIT1; } else { CP_WAIT0; }
        __syncthreads();
        if(c<9) ISSUE(c+3, (c+3)&3);
        uint32_t aB  = sbase + A_HI + (uint32_t)c*2048;
        uint32_t aBl = sbase + A_LO + (uint32_t)c*2048;
        uint32_t bB  = sbase + BOFF + (uint32_t)(c&3)*BSTG;

        uint32_t ah[2][4], al[2][4], bb[3][4];
        LDSM4(ah[0], aB  + aOff[0]);
        LDSM4(ah[1], aB  + aOff[1]);
        LDSM4(al[0], aBl + aOff[0]);
        LDSM4(al[1], aBl + aOff[1]);
        #pragma unroll
        for(int i=0;i<3;i++) LDSM4(bb[i], bB + bOff[i]);
        PASS(ah, bb)
        PASS(al, bb)
        #pragma unroll
        for(int i=0;i<3;i++) LDSM4(bb[i], bB + 6144 + bOff[i]);
        PASS(ah, bb)
    }
#undef PASS

    // ---------------- epilogue: bias + LN2 + gelu + residual ----------------
    float* red1 = (float*)(smem + RED_OFF);
    float* red2 = red1 + 256;
    float* musm = red1 + 512;
    float* rssm = red1 + 576;
    float* redL = red1 + 640;

    float s1[2][2] = {{0.f,0.f},{0.f,0.f}};
    float s2[2][2] = {{0.f,0.f},{0.f,0.f}};
    #pragma unroll
    for(int mt=0;mt<2;mt++)
        #pragma unroll
        for(int nt=0;nt<6;nt++){
            int col = wn*48 + nt*8 + qi*2;
            float b0 = par[col], b1 = par[col+1];
            acc[mt][nt][0] += b0; acc[mt][nt][1] += b1;
            acc[mt][nt][2] += b0; acc[mt][nt][3] += b1;
            #pragma unroll
            for(int h=0;h<2;h++){
                float v0 = acc[mt][nt][h*2], v1 = acc[mt][nt][h*2+1];
                s1[mt][h] += v0 + v1;
                s2[mt][h] += v0*v0 + v1*v1;
            }
        }
    __syncthreads();   // all warps past mainloop: A and B smem regions dead

    if(LAST){
        // stream in proj weight image (24.6KB) into B region
        #pragma unroll
        for(int m=0;m<6;m++){
            int id = tid + m*256;
            int ch = id >> 7;
            int rem = id & 127;
            int d = rem >> 6;
            int rem2 = rem & 63;
            int o = rem2 >> 1, s = rem2 & 1;
            uint32_t dst = sbase + BOFF + (uint32_t)ch*2048 + (uint32_t)d*1024
                         + (uint32_t)o*32 + (uint32_t)((s ^ ((o>>2)&1)) << 4);
            CP16(dst, (const uint4*)g_pr + id);
        }
        CP_COMMIT;
    }

    #pragma unroll
    for(int mt=0;mt<2;mt++)
        #pragma unroll
        for(int h=0;h<2;h++){
            float a = s1[mt][h], b2 = s2[mt][h];
            a  += __shfl_xor_sync(0xffffffffu, a, 1);
            a  += __shfl_xor_sync(0xffffffffu, a, 2);
            b2 += __shfl_xor_sync(0xffffffffu, b2, 1);
            b2 += __shfl_xor_sync(0xffffffffu, b2, 2);
            if(qi==0){
                int row = wm*32 + mt*16 + h*8 + q;
                red1[wn*64 + row] = a;
                red2[wn*64 + row] = b2;
            }
        }
    __syncthreads();
    if(tid < 64){
        float t1 = red1[tid] + red1[64+tid] + red1[128+tid] + red1[192+tid];
        float t2 = red2[tid] + red2[64+tid] + red2[128+tid] + red2[192+tid];
        float mu = t1*(1.0f/H);
        musm[tid] = mu;
        rssm[tid] = rsqrtf(t2*(1.0f/H) - mu*mu + 1e-5f);
    }
    __syncthreads();

    const float* lg = par + 192;
    const float* lb = par + 384;
    #pragma unroll
    for(int mt=0;mt<2;mt++)
        #pragma unroll
        for(int h=0;h<2;h++){
            int r = wm*32 + mt*16 + h*8 + q;
            float mu = musm[r], rs = rssm[r];
            long long grow = bt0 + r;
            float xa = 0.f;
            const float* ginrow = gin + grow*H;
            if(FIRST) xa = x[((long long)b*2)*T + t0 + r];
            float* goutrow = gout + grow*H;
            int xr = (r>>2)&1;
            #pragma unroll
            for(int nt=0;nt<6;nt++){
                int col = wn*48 + nt*8 + qi*2;
                float v0 = acc[mt][nt][h*2], v1 = acc[mt][nt][h*2+1];
                float res0, res1;
                if(FIRST){
                    res0 = __ldg(in_w + col)*xa   + __ldg(in_b + col);
                    res1 = __ldg(in_w + col+1)*xa + __ldg(in_b + col+1);
                } else {
                    float2 rv = *(const float2*)(ginrow + col);
                    res0 = rv.x; res1 = rv.y;
                }
                float o0 = gelu_fast((v0-mu)*rs*lg[col]   + lb[col])   + res0;
                float o1 = gelu_fast((v1-mu)*rs*lg[col+1] + lb[col+1]) + res1;
                if(!LAST){
                    *(float2*)(goutrow + col) = make_float2(o0, o1);
                } else {
                    uint32_t ph, pl;
                    split2(o0, o1, ph, pl);
                    uint32_t off = (uint32_t)(col>>4)*2048 + (uint32_t)r*32
                                 + (uint32_t)((((col>>3)&1) ^ xr) << 4)
                                 + (uint32_t)(col&7)*2;
                    *(uint32_t*)(smem + A_HI + off) = ph;
                    *(uint32_t*)(smem + A_LO + off) = pl;
                }
            }
        }

    if(!LAST) return;

    // ---------------- last layer: proj GEMM (64x32x192) ----------------
    CP_WAIT0;
    __syncthreads();

    int wm2 = wid & 3, wn2 = wid >> 2;
    uint32_t a2Off, b2Off;
    {
        int row = wm2*16 + (g2&1)*8 + lr;
        a2Off = (uint32_t)row*32 + (uint32_t)(((g2>>1) ^ ((row>>2)&1)) << 4);
        int o = wn2*16 + (g2>>1)*8 + lr;
        b2Off = (uint32_t)o*32 + (uint32_t)(((g2&1) ^ ((o>>2)&1)) << 4);
    }
    float acc2[2][4];
    #pragma unroll
    for(int nt=0;nt<2;nt++)
        #pragma unroll
        for(int r2=0;r2<4;r2++) acc2[nt][r2] = 0.f;

    #pragma unroll 1
    for(int ch=0; ch<12; ch++){
        uint32_t aB  = sbase + A_HI + (uint32_t)ch*2048;
        uint32_t aBl = sbase + A_LO + (uint32_t)ch*2048;
        uint32_t bB  = sbase + BOFF + (uint32_t)ch*2048;
        uint32_t ah[4], al[4], bb[4];
        LDSM4(ah, aB  + a2Off);
        LDSM4(al, aBl + a2Off);
        LDSM4(bb, bB + b2Off);
        MMA16816(acc2[0], ah, bb[0], bb[1]);
        MMA16816(acc2[1], ah, bb[2], bb[3]);
        MMA16816(acc2[0], al, bb[0], bb[1]);
        MMA16816(acc2[1], al, bb[2], bb[3]);
        LDSM4(bb, bB + 1024 + b2Off);
        MMA16816(acc2[0], ah, bb[0], bb[1]);
        MMA16816(acc2[1], ah, bb[2], bb[3]);
    }

    float* Psm = (float*)(smem + PSM_OFF);
    #pragma unroll
    for(int h=0;h<2;h++){
        int row = wm2*16 + h*8 + q;
        #pragma unroll
        for(int nt=0;nt<2;nt++){
            int col = wn2*16 + nt*8 + qi*2;
            Psm[row*33 + col]   = acc2[nt][h*2];
            Psm[row*33 + col+1] = acc2[nt][h*2+1];
        }
    }
    __syncthreads();

    // ---------------- spline math: tid<64, one row each ----------------
    float lv = 0.f;
    if(tid < 64){
        int t = t0 + tid;
        float mask = xmask[(long long)b*T + t];
        float p[NJ];
        #pragma unroll
        for(int j=0;j<NJ;j++) p[j] = (Psm[tid*33 + j] + __ldg(proj_b + j)) * mask;

        const float inv_dn = 0.07216878364870323f;

        float cwv[BINS+1], wsv[BINS];
        {
            float m = -1e30f;
            #pragma unroll
            for(int j=0;j<BINS;j++) m = fmaxf(m, p[j]);
            float e[BINS]; float ssum = 0.f;
            #pragma unroll
            for(int j=0;j<BINS;j++){ e[j] = __expf((p[j]-m)*inv_dn); ssum += e[j]; }
            float inv = 1.0f/ssum;
            float cum = 0.f;
            cwv[0] = -TAILV;
            #pragma unroll
            for(int j=0;j<BINS;j++){
                float wj = 1e-3f + 0.99f*e[j]*inv;
                cum += wj;
                cwv[j+1] = 2.0f*TAILV*cum - TAILV;
            }
            cwv[BINS] = TAILV;
            #pragma unroll
            for(int j=0;j<BINS;j++) wsv[j] = cwv[j+1]-cwv[j];
        }
        float chv[BINS+1], hsv[BINS];
        {
            float m = -1e30f;
            #pragma unroll
            for(int j=0;j<BINS;j++) m = fmaxf(m, p[BINS+j]);
            float e[BINS]; float ssum = 0.f;
            #pragma unroll
            for(int j=0;j<BINS;j++){ e[j] = __expf((p[BINS+j]-m)*inv_dn); ssum += e[j]; }
            float inv = 1.0f/ssum;
            float cum = 0.f;
            chv[0] = -TAILV;
            #pragma unroll
            for(int j=0;j<BINS;j++){
                float hj = 1e-3f + 0.99f*e[j]*inv;
                cum += hj;
                chv[j+1] = 2.0f*TAILV*cum - TAILV;
            }
            chv[BINS] = TAILV;
            #pragma unroll
            for(int j=0;j<BINS;j++) hsv[j] = chv[j+1]-chv[j];
        }
        float derv[BINS+1];
        derv[0] = 1.0f; derv[BINS] = 1.0f;
        #pragma unroll
        for(int k=1;k<BINS;k++){
            float u = p[2*BINS + k - 1];
            float sp = (u > 20.f) ? u : __logf(1.0f + __expf(u));
            derv[k] = 1e-3f + sp;
        }

        float xbv = x[((long long)b*2+1)*T + t];
        bool inside = (xbv >= -TAILV) && (xbv <= TAILV);
        float xc = fminf(fmaxf(xbv, -TAILV), TAILV);
        int idx = 0;
        #pragma unroll
        for(int j=0;j<BINS;j++) idx += (xc >= cwv[j]) ? 1 : 0;
        idx -= 1;
        idx = max(0, min(BINS-1, idx));

        float icw=0.f, ibw=1.f, ich=0.f, ih=1.f, dk=1.f, dk1=1.f;
        #pragma unroll
        for(int j=0;j<BINS;j++){
            bool sel = (idx==j);
            icw = sel ? cwv[j]   : icw;
            ibw = sel ? wsv[j]   : ibw;
            ich = sel ? chv[j]   : ich;
            ih  = sel ? hsv[j]   : ih;
            dk  = sel ? derv[j]  : dk;
            dk1 = sel ? derv[j+1]: dk1;
        }

        float idl = ih/ibw;
        float th  = (xc - icw)/ibw;
        float t1m = th*(1.0f - th);
        float num = ih*(idl*th*th + dk*t1m);
        float den = idl + (dk + dk1 - 2.0f*idl)*t1m;
        float outv = ich + num/den;
        float omt = 1.0f - th;
        float dnum = idl*idl*(dk1*th*th + 2.0f*idl*t1m + dk*omt*omt);
        float lad = __logf(dnum) - 2.0f*__logf(den);

        float xb2 = inside ? outv : xbv;
        lad = inside ? lad : 0.0f;

        float xav = x[((long long)b*2)*T + t];
        out[(long long)b*2*T + t]     = xav*mask;
        out[(long long)b*2*T + T + t] = xb2*mask;
        lv = lad*mask;
    }

    if(wid < 2){
        #pragma unroll
        for(int o=16;o>0;o>>=1) lv += __shfl_xor_sync(0xffffffffu, lv, o);
        if(lane == 0) redL[wid] = lv;
    }
    __syncthreads();
    if(tid == 0)
        atomicAdd(out + (long long)B*2*T + b, redL[0] + redL[1]);
}

// ---------------------------------------------------------------------------
extern "C" void kernel_launch(void* const* d_in, const int* in_sizes, int n_in,
                              void* d_out, int out_size)
{
    const float* x      = (const float*)d_in[0];
    const float* xmask  = (const float*)d_in[1];
    const float* in_w   = (const float*)d_in[2];
    const float* in_b   = (const float*)d_in[3];
    const float* dw_w   = (const float*)d_in[4];
    const float* dw_b   = (const float*)d_in[5];
    const float* ln1_g  = (const float*)d_in[6];
    const float* ln1_b  = (const float*)d_in[7];
    const float* pw_w   = (const float*)d_in[8];
    const float* pw_b   = (const float*)d_in[9];
    const float* ln2_g  = (const float*)d_in[10];
    const float* ln2_b  = (const float*)d_in[11];
    const float* proj_w = (const float*)d_in[12];
    const float* proj_b = (const float*)d_in[13];
    float* out = (float*)d_out;

    cudaFuncSetAttribute(k_fused<true,false>,  cudaFuncAttributeMaxDynamicSharedMemorySize, FUSED_SMEM_BYTES);
    cudaFuncSetAttribute(k_fused<false,false>, cudaFuncAttributeMaxDynamicSharedMemorySize, FUSED_SMEM_BYTES);
    cudaFuncSetAttribute(k_fused<false,true>,  cudaFuncAttributeMaxDynamicSharedMemorySize, FUSED_SMEM_BYTES);

    k_zero<<<1, 32>>>(out);
    k_zero<<<1, 32>>>(out);
    k_zero<<<1, 32>>>(out);
    k_prep<<<(3*H*H + 255)/256, 256>>>(pw_w, proj_w, dw_w);
    k_fused<true,false><<<BT/64, 256, FUSED_SMEM_BYTES>>>(0, 1, x, in_w, in_b, xmask,
        dw_b, ln1_g, ln1_b, pw_b, ln2_g, ln2_b, proj_b, out);
    k_fused<false,false><<<BT/64, 256, FUSED_SMEM_BYTES>>>(1, 3, x, in_w, in_b, xmask,
        dw_b, ln1_g, ln1_b, pw_b, ln2_g, ln2_b, proj_b, out);
    k_fused<false,true><<<BT/64, 256, FUSED_SMEM_BYTES>>>(2, 9, x, in_w, in_b, xmask,
        dw_b, ln1_g, ln1_b, pw_b, ln2_g, ln2_b, proj_b, out);
}

// round 15
// speedup vs baseline: 1.1422x; 1.0080x over previous
#include <cuda_runtime.h>
#include <cuda_bf16.h>
#include <math.h>
#include <stdint.h>

#define B 32
#define T 8192
#define H 192
#define BT (B*T)
#define BINS 10
#define TAILV 5.0f
#define NJ 29

// residual stream ping-pong buffers (f32), layout [b][t][c]
__device__ float g_x0[(size_t)BT*H];
__device__ float g_x1[(size_t)BT*H];
// chunk-ordered pw weight image: [layer][chunk12][dtype2][o192][seg2][8bf16]
__device__ __align__(16) __nv_bfloat16 g_wr[3*12*2*192*16];
// chunk-ordered proj weight image: [chunk12][dtype2][o32][seg2][8bf16]
__device__ __align__(16) __nv_bfloat16 g_pr[12*2*32*16];
// transposed depthwise weights: [layer][tap][c]
__device__ float g_dwt[3*3*192];

// fast gelu: v - v/(exp(2c(v+av^3))+1); tails exact, |err|<~2e-4 abs
__device__ __forceinline__ float gelu_fast(float v){
    float t2 = 1.5957691216057308f * fmaf(0.044715f*v, v*v, v);
    float e = __expf(t2);
    float r;
    asm("rcp.approx.f32 %0, %1;" : "=f"(r) : "f"(e + 1.0f));
    return fmaf(-v, r, v);
}

// split (y0,y1) into packed bf16x2 hi + lo parts
__device__ __forceinline__ void split2(float y0, float y1, uint32_t& ph, uint32_t& pl){
    uint32_t h;
    asm("cvt.rn.bf16x2.f32 %0, %1, %2;" : "=r"(h) : "f"(y1), "f"(y0));
    float h0 = __uint_as_float(h << 16);
    float h1 = __uint_as_float(h & 0xffff0000u);
    asm("cvt.rn.bf16x2.f32 %0, %1, %2;" : "=r"(pl) : "f"(y1 - h1), "f"(y0 - h0));
    ph = h;
}

__device__ __forceinline__ uint32_t smem_u32(const void* p){
    uint32_t a;
    asm("{ .reg .u64 t; cvta.to.shared.u64 t, %1; cvt.u32.u64 %0, t; }" : "=r"(a) : "l"(p));
    return a;
}

#define LDSM4(r, addr) \
    asm volatile("ldmatrix.sync.aligned.m8n8.x4.shared.b16 {%0,%1,%2,%3}, [%4];" \
        : "=r"((r)[0]),"=r"((r)[1]),"=r"((r)[2]),"=r"((r)[3]) : "r"(addr))

#define MMA16816(d, a, b0, b1) \
    asm volatile("mma.sync.aligned.m16n8k16.row.col.f32.bf16.bf16.f32 " \
        "{%0,%1,%2,%3},{%4,%5,%6,%7},{%8,%9},{%0,%1,%2,%3};" \
        : "+f"((d)[0]),"+f"((d)[1]),"+f"((d)[2]),"+f"((d)[3]) \
        : "r"((a)[0]),"r"((a)[1]),"r"((a)[2]),"r"((a)[3]), "r"(b0),"r"(b1))

#define CP16(dst, src) \
    asm volatile("cp.async.cg.shared.global [%0], [%1], 16;" :: "r"(dst), "l"(src))
#define CP_COMMIT asm volatile("cp.async.commit_group;" ::: "memory")
#define CP_WAIT2  asm volatile("cp.async.wait_group 2;" ::: "memory")
#define CP_WAIT1  asm volatile("cp.async.wait_group 1;" ::: "memory")
#define CP_WAIT0  asm volatile("cp.async.wait_group 0;" ::: "memory")

// ---------------------------------------------------------------------------
// prep: pw chunk image, proj chunk image, dw transpose, zero logdet
__global__ void k_prep(const float* __restrict__ pw_w,
                       const float* __restrict__ proj_w,
                       const float* __restrict__ dw_w,
                       float* __restrict__ out)
{
    int i = blockIdx.x*256 + threadIdx.x;
    if (i < B) out[(long long)B*2*T + i] = 0.0f;
    if (i < 3*H*H){
        int L = i / (H*H);
        int r = i - L*(H*H);
        int o = r / H, k = r - o*H;
        float w = pw_w[i];
        __nv_bfloat16 hb = __float2bfloat16(w);
        __nv_bfloat16 lb = __float2bfloat16(w - __bfloat162float(hb));
        int ch = k >> 4;
        int s  = (k >> 3) & 1;
        int j  = k & 7;
        size_t base = (((size_t)(L*12 + ch)*2)*192 + o)*16 + s*8 + j;
        g_wr[base]        = hb;
        g_wr[base + 3072] = lb;
    }
    if (i < 12*2*32*16){
        int ch = i >> 10;
        int rem = i & 1023;
        int d = rem >> 9;
        int rem2 = rem & 511;
        int o = rem2 >> 4;
        int s = (rem2 >> 3) & 1;
        int j = rem2 & 7;
        int k = ch*16 + s*8 + j;
        float w = (o < NJ) ? proj_w[o*H + k] : 0.0f;
        __nv_bfloat16 hb = __float2bfloat16(w);
        __nv_bfloat16 lb = __float2bfloat16(w - __bfloat162float(hb));
        g_pr[i] = d ? lb : hb;
    }
    if (i < 3*3*H){
        int L = i / (3*H);
        int rem = i - L*(3*H);
        int c = rem / 3, k = rem - c*3;
        g_dwt[L*(3*H) + k*H + c] = dw_w[i];
    }
}

// ---------------------------------------------------------------------------
// FUSED kernel (templated on FIRST/LAST): conv(dil)+LN1+gelu -> split-bf16
// GEMM (W streamed, 4-stage ring, 1 chunk/barrier) -> bias+LN2+gelu+residual.
// LAST adds: proj GEMM + RQ-spline + logdet, in-CTA.
#define A_HI    0
#define A_LO    24576
#define BOFF    49152
#define BSTG    12288
#define PSM_OFF (BOFF + 24576)
#define PAR_OFF (BOFF + 4*BSTG)        // 98304
#define RED_OFF (PAR_OFF + 2304)
#define FUSED_SMEM_BYTES (RED_OFF + 2592)

template<bool FIRST, bool LAST>
__global__ void __launch_bounds__(256,2) k_fused(int layer, int dil,
    const float* __restrict__ x,
    const float* __restrict__ in_w, const float* __restrict__ in_b,
    const float* __restrict__ xmask,
    const float* __restrict__ dw_b,
    const float* __restrict__ ln1_g, const float* __restrict__ ln1_b,
    const float* __restrict__ pw_b,
    const float* __restrict__ ln2_g, const float* __restrict__ ln2_b,
    const float* __restrict__ proj_b,
    float* __restrict__ out)
{
    extern __shared__ char smem[];
    uint32_t sbase = smem_u32(smem);
    int tid = threadIdx.x;
    int wid = tid >> 5, lane = tid & 31;
    int wm = wid & 1, wn = wid >> 1;          // 2 warps in M, 4 in N
    int q = lane >> 2, qi = lane & 3;
    long long bt0 = (long long)blockIdx.x * 64;
    int b  = (int)(bt0 >> 13);
    int t0 = (int)(bt0 & (T-1));
    const float* gin = LAST ? g_x1 : g_x0;
    float* gout = FIRST ? g_x0 : g_x1;

    uint32_t dstB[3];
    #pragma unroll
    for(int m=0;m<3;m++){
        int id = tid + m*256;
        int d = id / 384;
        int rem = id - d*384;
        int o = rem >> 1, s = rem & 1;
        dstB[m] = (uint32_t)d*6144 + (uint32_t)o*32
                + (uint32_t)((s ^ ((o>>2)&1)) << 4);
    }
    const uint4* wrp = (const uint4*)g_wr + (size_t)layer*9216 + tid;

#define ISSUE(cc, st) do { \
    uint32_t _bs = sbase + BOFF + (uint32_t)(st)*BSTG; \
    const uint4* _w = wrp + (cc)*768; \
    CP16(_bs + dstB[0], _w); \
    CP16(_bs + dstB[1], _w + 256); \
    CP16(_bs + dstB[2], _w + 512); \
    CP_COMMIT; \
} while(0)

    ISSUE(0, 0);
    ISSUE(1, 1);
    ISSUE(2, 2);

    float* par = (float*)(smem + PAR_OFF);
    if(tid < 192){
        par[tid]       = pw_b[layer*H + tid];
        par[192 + tid] = ln2_g[layer*H + tid];
        par[384 + tid] = ln2_b[layer*H + tid];
    }

    // ---------------- phase 1: conv + LN1 + gelu -> A smem ----------------
    {
        int c0 = lane*6;
        float w0[6], w1[6], w2[6], bbv[6], ggv[6], gbv[6];
        const float* wt = g_dwt + layer*(3*H);
        #pragma unroll
        for(int p=0;p<3;p++){
            float2 a = *(const float2*)(wt + c0 + p*2);
            w0[p*2]=a.x; w0[p*2+1]=a.y;
            float2 bq = *(const float2*)(wt + H + c0 + p*2);
            w1[p*2]=bq.x; w1[p*2+1]=bq.y;
            float2 cq = *(const float2*)(wt + 2*H + c0 + p*2);
            w2[p*2]=cq.x; w2[p*2+1]=cq.y;
            float2 d = *(const float2*)(dw_b + layer*H + c0 + p*2);
            bbv[p*2]=d.x; bbv[p*2+1]=d.y;
            float2 e = *(const float2*)(ln1_g + layer*H + c0 + p*2);
            ggv[p*2]=e.x; ggv[p*2+1]=e.y;
            float2 f = *(const float2*)(ln1_b + layer*H + c0 + p*2);
            gbv[p*2]=f.x; gbv[p*2+1]=f.y;
        }
        float iw[6], ib[6];
        if(FIRST){
            #pragma unroll
            for(int p=0;p<3;p++){
                float2 a = *(const float2*)(in_w + c0 + p*2);
                iw[p*2]=a.x; iw[p*2+1]=a.y;
                float2 bq = *(const float2*)(in_b + c0 + p*2);
                ib[p*2]=bq.x; ib[p*2+1]=bq.y;
            }
        }
        const float* mrow = xmask + (long long)b*T;
        const float* xrowa = x + ((long long)b*2)*T;

        #pragma unroll 4
        for(int rr=0; rr<8; rr++){
            int r = wid*8 + rr;
            long long grow = bt0 + r;
            int t = t0 + r;
            int tm = t - dil, tp = t + dil;
            bool hm = (tm >= 0), hp = (tp < T);
            float mm = hm ? mrow[tm] : 0.f;
            float m0 = mrow[t];
            float mp = hp ? mrow[tp] : 0.f;

            float xm[6], xz[6], xp[6];
            if(FIRST){
                float xam = hm ? xrowa[tm] : 0.f;
                float xa0 = xrowa[t];
                float xap = hp ? xrowa[tp] : 0.f;
                #pragma unroll
                for(int k=0;k<6;k++){
                    xm[k] = iw[k]*xam + ib[k];
                    xz[k] = iw[k]*xa0 + ib[k];
                    xp[k] = iw[k]*xap + ib[k];
                }
            } else {
                const float* base = gin + grow*H + c0;
                #pragma unroll
                for(int p=0;p<3;p++){
                    float2 a = *(const float2*)(base + p*2);
                    xz[p*2]=a.x; xz[p*2+1]=a.y;
                }
                if(hm){
                    const float* bmp = base - (long long)dil*H;
                    #pragma unroll
                    for(int p=0;p<3;p++){
                        float2 a = *(const float2*)(bmp + p*2);
                        xm[p*2]=a.x; xm[p*2+1]=a.y;
                    }
                } else {
                    #pragma unroll
                    for(int k=0;k<6;k++) xm[k]=0.f;
                }
                if(hp){
                    const float* bpp = base + (long long)dil*H;
                    #pragma unroll
                    for(int p=0;p<3;p++){
                        float2 a = *(const float2*)(bpp + p*2);
                        xp[p*2]=a.x; xp[p*2+1]=a.y;
                    }
                } else {
                    #pragma unroll
                    for(int k=0;k<6;k++) xp[k]=0.f;
                }
            }

            float v[6];
            float s=0.f, sq=0.f;
            #pragma unroll
            for(int k=0;k<6;k++){
                float rv = w0[k]*(xm[k]*mm) + w1[k]*(xz[k]*m0) + w2[k]*(xp[k]*mp) + bbv[k];
                v[k]=rv; s+=rv; sq+=rv*rv;
            }
            #pragma unroll
            for(int o=16;o>0;o>>=1){
                s  += __shfl_xor_sync(0xffffffffu, s,  o);
                sq += __shfl_xor_sync(0xffffffffu, sq, o);
            }
            float mu = s*(1.0f/H);
            float rs = rsqrtf(sq*(1.0f/H) - mu*mu + 1e-5f);

            int xr = (r>>2)&1;
            #pragma unroll
            for(int p=0;p<3;p++){
                float y0 = gelu_fast((v[p*2]  -mu)*rs*ggv[p*2]   + gbv[p*2]);
                float y1 = gelu_fast((v[p*2+1]-mu)*rs*ggv[p*2+1] + gbv[p*2+1]);
                uint32_t ph, pl;
                split2(y0, y1, ph, pl);
                int c = c0 + 2*p;
                uint32_t off = (uint32_t)(c>>4)*2048 + (uint32_t)r*32
                             + (uint32_t)((((c>>3)&1) ^ xr) << 4) + (uint32_t)(c&7)*2;
                *(uint32_t*)(smem + A_HI + off) = ph;
                *(uint32_t*)(smem + A_LO + off) = pl;
            }
        }
    }

    // ---------------- phase 2: k-loop (12 chunks of k=16) ----------------
    int g2 = lane >> 3, lr = lane & 7;
    uint32_t aOff[2];
    #pragma unroll
    for(int mt=0;mt<2;mt++){
        int row = wm*32 + mt*16 + (g2&1)*8 + lr;
        aOff[mt] = (uint32_t)row*32 + (uint32_t)(((g2>>1) ^ ((row>>2)&1)) << 4);
    }
    uint32_t bOff[3];
    #pragma unroll
    for(int i=0;i<3;i++){
        int o = wn*48 + i*16 + (g2>>1)*8 + lr;
        bOff[i] = (uint32_t)o*32 + (uint32_t)(((g2&1) ^ ((o>>2)&1)) << 4);
    }

    float acc[2][6][4];
    #pragma unroll
    for(int mt=0;mt<2;mt++)
        #pragma unroll
        for(int nt=0;nt<6;nt++)
            #pragma unroll
            for(int r2=0;r2<4;r2++) acc[mt][nt][r2] = 0.f;

#define PASS(AH, BB) \
    _Pragma("unroll") \
    for(int mt=0;mt<2;mt++){ \
        _Pragma("unroll") \
        for(int i=0;i<3;i++){ \
            MMA16816(acc[mt][2*i],   AH[mt], BB[i][0], BB[i][1]); \
            MMA16816(acc[mt][2*i+1], AH[mt], BB[i][2], BB[i][3]); \
        } \
    }

    #pragma unroll 1
    for(int c=0;c<12;c++){
        if(c<10){ CP_WAIT2; } else if(c==10){ CP_WAIT1; } else { CP_WAIT0; }
        __syncthreads();
        if(c<9) ISSUE(c+3, (c+3)&3);
        uint32_t aB  = sbase + A_HI + (uint32_t)c*2048;
        uint32_t aBl = sbase + A_LO + (uint32_t)c*2048;
        uint32_t bB  = sbase + BOFF + (uint32_t)(c&3)*BSTG;

        uint32_t ah[2][4], al[2][4], bb[3][4];
        LDSM4(ah[0], aB  + aOff[0]);
        LDSM4(ah[1], aB  + aOff[1]);
        LDSM4(al[0], aBl + aOff[0]);
        LDSM4(al[1], aBl + aOff[1]);
        #pragma unroll
        for(int i=0;i<3;i++) LDSM4(bb[i], bB + bOff[i]);
        PASS(ah, bb)
        PASS(al, bb)
        #pragma unroll
        for(int i=0;i<3;i++) LDSM4(bb[i], bB + 6144 + bOff[i]);
        PASS(ah, bb)
    }
#undef PASS

    // ---------------- epilogue: bias + LN2 + gelu + residual ----------------
    float* red1 = (float*)(smem + RED_OFF);
    float* red2 = red1 + 256;
    float* musm = red1 + 512;
    float* rssm = red1 + 576;
    float* redL = red1 + 640;

    float s1[2][2] = {{0.f,0.f},{0.f,0.f}};
    float s2[2][2] = {{0.f,0.f},{0.f,0.f}};
    #pragma unroll
    for(int mt=0;mt<2;mt++)
        #pragma unroll
        for(int nt=0;nt<6;nt++){
            int col = wn*48 + nt*8 + qi*2;
            float b0 = par[col], b1 = par[col+1];
            acc[mt][nt][0] += b0; acc[mt][nt][1] += b1;
            acc[mt][nt][2] += b0; acc[mt][nt][3] += b1;
            #pragma unroll
            for(int h=0;h<2;h++){
                float v0 = acc[mt][nt][h*2], v1 = acc[mt][nt][h*2+1];
                s1[mt][h] += v0 + v1;
                s2[mt][h] += v0*v0 + v1*v1;
            }
        }
    __syncthreads();   // all warps past mainloop: A and B smem regions dead

    if(LAST){
        // stream in proj weight image (24.6KB) into B region
        #pragma unroll
        for(int m=0;m<6;m++){
            int id = tid + m*256;
            int ch = id >> 7;
            int rem = id & 127;
            int d = rem >> 6;
            int rem2 = rem & 63;
            int o = rem2 >> 1, s = rem2 & 1;
            uint32_t dst = sbase + BOFF + (uint32_t)ch*2048 + (uint32_t)d*1024
                         + (uint32_t)o*32 + (uint32_t)((s ^ ((o>>2)&1)) << 4);
            CP16(dst, (const uint4*)g_pr + id);
        }
        CP_COMMIT;
    }

    #pragma unroll
    for(int mt=0;mt<2;mt++)
        #pragma unroll
        for(int h=0;h<2;h++){
            float a = s1[mt][h], b2 = s2[mt][h];
            a  += __shfl_xor_sync(0xffffffffu, a, 1);
            a  += __shfl_xor_sync(0xffffffffu, a, 2);
            b2 += __shfl_xor_sync(0xffffffffu, b2, 1);
            b2 += __shfl_xor_sync(0xffffffffu, b2, 2);
            if(qi==0){
                int row = wm*32 + mt*16 + h*8 + q;
                red1[wn*64 + row] = a;
                red2[wn*64 + row] = b2;
            }
        }
    __syncthreads();
    if(tid < 64){
        float t1 = red1[tid] + red1[64+tid] + red1[128+tid] + red1[192+tid];
        float t2 = red2[tid] + red2[64+tid] + red2[128+tid] + red2[192+tid];
        float mu = t1*(1.0f/H);
        musm[tid] = mu;
        rssm[tid] = rsqrtf(t2*(1.0f/H) - mu*mu + 1e-5f);
    }
    __syncthreads();

    const float* lg = par + 192;
    const float* lb = par + 384;
    #pragma unroll
    for(int mt=0;mt<2;mt++)
        #pragma unroll
        for(int h=0;h<2;h++){
            int r = wm*32 + mt*16 + h*8 + q;
            float mu = musm[r], rs = rssm[r];
            long long grow = bt0 + r;
            float xa = 0.f;
            const float* ginrow = gin + grow*H;
            if(FIRST) xa = x[((long long)b*2)*T + t0 + r];
            float* goutrow = gout + grow*H;
            int xr = (r>>2)&1;
            #pragma unroll
            for(int nt=0;nt<6;nt++){
                int col = wn*48 + nt*8 + qi*2;
                float v0 = acc[mt][nt][h*2], v1 = acc[mt][nt][h*2+1];
                float res0, res1;
                if(FIRST){
                    res0 = __ldg(in_w + col)*xa   + __ldg(in_b + col);
                    res1 = __ldg(in_w + col+1)*xa + __ldg(in_b + col+1);
                } else {
                    float2 rv = *(const float2*)(ginrow + col);
                    res0 = rv.x; res1 = rv.y;
                }
                float o0 = gelu_fast((v0-mu)*rs*lg[col]   + lb[col])   + res0;
                float o1 = gelu_fast((v1-mu)*rs*lg[col+1] + lb[col+1]) + res1;
                if(!LAST){
                    *(float2*)(goutrow + col) = make_float2(o0, o1);
                } else {
                    uint32_t ph, pl;
                    split2(o0, o1, ph, pl);
                    uint32_t off = (uint32_t)(col>>4)*2048 + (uint32_t)r*32
                                 + (uint32_t)((((col>>3)&1) ^ xr) << 4)
                                 + (uint32_t)(col&7)*2;
                    *(uint32_t*)(smem + A_HI + off) = ph;
                    *(uint32_t*)(smem + A_LO + off) = pl;
                }
            }
        }

    if(!LAST) return;

    // ---------------- last layer: proj GEMM (64x32x192) ----------------
    CP_WAIT0;
    __syncthreads();

    int wm2 = wid & 3, wn2 = wid >> 2;
    uint32_t a2Off, b2Off;
    {
        int row = wm2*16 + (g2&1)*8 + lr;
        a2Off = (uint32_t)row*32 + (uint32_t)(((g2>>1) ^ ((row>>2)&1)) << 4);
        int o = wn2*16 + (g2>>1)*8 + lr;
        b2Off = (uint32_t)o*32 + (uint32_t)(((g2&1) ^ ((o>>2)&1)) << 4);
    }
    float acc2[2][4];
    #pragma unroll
    for(int nt=0;nt<2;nt++)
        #pragma unroll
        for(int r2=0;r2<4;r2++) acc2[nt][r2] = 0.f;

    #pragma unroll 1
    for(int ch=0; ch<12; ch++){
        uint32_t aB  = sbase + A_HI + (uint32_t)ch*2048;
        uint32_t aBl = sbase + A_LO + (uint32_t)ch*2048;
        uint32_t bB  = sbase + BOFF + (uint32_t)ch*2048;
        uint32_t ah[4], al[4], bb[4];
        LDSM4(ah, aB  + a2Off);
        LDSM4(al, aBl + a2Off);
        LDSM4(bb, bB + b2Off);
        MMA16816(acc2[0], ah, bb[0], bb[1]);
        MMA16816(acc2[1], ah, bb[2], bb[3]);
        MMA16816(acc2[0], al, bb[0], bb[1]);
        MMA16816(acc2[1], al, bb[2], bb[3]);
        LDSM4(bb, bB + 1024 + b2Off);
        MMA16816(acc2[0], ah, bb[0], bb[1]);
        MMA16816(acc2[1], ah, bb[2], bb[3]);
    }

    float* Psm = (float*)(smem + PSM_OFF);
    #pragma unroll
    for(int h=0;h<2;h++){
        int row = wm2*16 + h*8 + q;
        #pragma unroll
        for(int nt=0;nt<2;nt++){
            int col = wn2*16 + nt*8 + qi*2;
            Psm[row*33 + col]   = acc2[nt][h*2];
            Psm[row*33 + col+1] = acc2[nt][h*2+1];
        }
    }
    __syncthreads();

    // ---------------- spline math: tid<64, one row each ----------------
    float lv = 0.f;
    if(tid < 64){
        int t = t0 + tid;
        float mask = xmask[(long long)b*T + t];
        float p[NJ];
        #pragma unroll
        for(int j=0;j<NJ;j++) p[j] = (Psm[tid*33 + j] + __ldg(proj_b + j)) * mask;

        const float inv_dn = 0.07216878364870323f;

        float cwv[BINS+1], wsv[BINS];
        {
            float m = -1e30f;
            #pragma unroll
            for(int j=0;j<BINS;j++) m = fmaxf(m, p[j]);
            float e[BINS]; float ssum = 0.f;
            #pragma unroll
            for(int j=0;j<BINS;j++){ e[j] = __expf((p[j]-m)*inv_dn); ssum += e[j]; }
            float inv = 1.0f/ssum;
            float cum = 0.f;
            cwv[0] = -TAILV;
            #pragma unroll
            for(int j=0;j<BINS;j++){
                float wj = 1e-3f + 0.99f*e[j]*inv;
                cum += wj;
                cwv[j+1] = 2.0f*TAILV*cum - TAILV;
            }
            cwv[BINS] = TAILV;
            #pragma unroll
            for(int j=0;j<BINS;j++) wsv[j] = cwv[j+1]-cwv[j];
        }
        float chv[BINS+1], hsv[BINS];
        {
            float m = -1e30f;
            #pragma unroll
            for(int j=0;j<BINS;j++) m = fmaxf(m, p[BINS+j]);
            float e[BINS]; float ssum = 0.f;
            #pragma unroll
            for(int j=0;j<BINS;j++){ e[j] = __expf((p[BINS+j]-m)*inv_dn); ssum += e[j]; }
            float inv = 1.0f/ssum;
            float cum = 0.f;
            chv[0] = -TAILV;
            #pragma unroll
            for(int j=0;j<BINS;j++){
                float hj = 1e-3f + 0.99f*e[j]*inv;
                cum += hj;
                chv[j+1] = 2.0f*TAILV*cum - TAILV;
            }
            chv[BINS] = TAILV;
            #pragma unroll
            for(int j=0;j<BINS;j++) hsv[j] = chv[j+1]-chv[j];
        }
        float derv[BINS+1];
        derv[0] = 1.0f; derv[BINS] = 1.0f;
        #pragma unroll
        for(int k=1;k<BINS;k++){
            float u = p[2*BINS + k - 1];
            float sp = (u > 20.f) ? u : __logf(1.0f + __expf(u));
            derv[k] = 1e-3f + sp;
        }

        float xbv = x[((long long)b*2+1)*T + t];
        bool inside = (xbv >= -TAILV) && (xbv <= TAILV);
        float xc = fminf(fmaxf(xbv, -TAILV), TAILV);
        int idx = 0;
        #pragma unroll
        for(int j=0;j<BINS;j++) idx += (xc >= cwv[j]) ? 1 : 0;
        idx -= 1;
        idx = max(0, min(BINS-1, idx));

        float icw=0.f, ibw=1.f, ich=0.f, ih=1.f, dk=1.f, dk1=1.f;
        #pragma unroll
        for(int j=0;j<BINS;j++){
            bool sel = (idx==j);
            icw = sel ? cwv[j]   : icw;
            ibw = sel ? wsv[j]   : ibw;
            ich = sel ? chv[j]   : ich;
            ih  = sel ? hsv[j]   : ih;
            dk  = sel ? derv[j]  : dk;
            dk1 = sel ? derv[j+1]: dk1;
        }

        float idl = ih/ibw;
        float th  = (xc - icw)/ibw;
        float t1m = th*(1.0f - th);
        float num = ih*(idl*th*th + dk*t1m);
        float den = idl + (dk + dk1 - 2.0f*idl)*t1m;
        float outv = ich + num/den;
        float omt = 1.0f - th;
        float dnum = idl*idl*(dk1*th*th + 2.0f*idl*t1m + dk*omt*omt);
        float lad = __logf(dnum) - 2.0f*__logf(den);

        float xb2 = inside ? outv : xbv;
        lad = inside ? lad : 0.0f;

        float xav = x[((long long)b*2)*T + t];
        out[(long long)b*2*T + t]     = xav*mask;
        out[(long long)b*2*T + T + t] = xb2*mask;
        lv = lad*mask;
    }

    if(wid < 2){
        #pragma unroll
        for(int o=16;o>0;o>>=1) lv += __shfl_xor_sync(0xffffffffu, lv, o);
        if(lane == 0) redL[wid] = lv;
    }
    __syncthreads();
    if(tid == 0)
        atomicAdd(out + (long long)B*2*T + b, redL[0] + redL[1]);
}

// ---------------------------------------------------------------------------
extern "C" void kernel_launch(void* const* d_in, const int* in_sizes, int n_in,
                              void* d_out, int out_size)
{
    const float* x      = (const float*)d_in[0];
    const float* xmask  = (const float*)d_in[1];
    const float* in_w   = (const float*)d_in[2];
    const float* in_b   = (const float*)d_in[3];
    const float* dw_w   = (const float*)d_in[4];
    const float* dw_b   = (const float*)d_in[5];
    const float* ln1_g  = (const float*)d_in[6];
    const float* ln1_b  = (const float*)d_in[7];
    const float* pw_w   = (const float*)d_in[8];
    const float* pw_b   = (const float*)d_in[9];
    const float* ln2_g  = (const float*)d_in[10];
    const float* ln2_b  = (const float*)d_in[11];
    const float* proj_w = (const float*)d_in[12];
    const float* proj_b = (const float*)d_in[13];
    float* out = (float*)d_out;

    cudaFuncSetAttribute(k_fused<true,false>,  cudaFuncAttributeMaxDynamicSharedMemorySize, FUSED_SMEM_BYTES);
    cudaFuncSetAttribute(k_fused<false,false>, cudaFuncAttributeMaxDynamicSharedMemorySize, FUSED_SMEM_BYTES);
    cudaFuncSetAttribute(k_fused<false,true>,  cudaFuncAttributeMaxDynamicSharedMemorySize, FUSED_SMEM_BYTES);

    k_prep<<<(3*H*H + 255)/256, 256>>>(pw_w, proj_w, dw_w, out);
    k_fused<true,false><<<BT/64, 256, FUSED_SMEM_BYTES>>>(0, 1, x, in_w, in_b, xmask,
        dw_b, ln1_g, ln1_b, pw_b, ln2_g, ln2_b, proj_b, out);
    k_fused<false,false><<<BT/64, 256, FUSED_SMEM_BYTES>>>(1, 3, x, in_w, in_b, xmask,
        dw_b, ln1_g, ln1_b, pw_b, ln2_g, ln2_b, proj_b, out);
    k_fused<false,true><<<BT/64, 256, FUSED_SMEM_BYTES>>>(2, 9, x, in_w, in_b, xmask,
        dw_b, ln1_g, ln1_b, pw_b, ln2_g, ln2_b, proj_b, out);
}